// round 9
// baseline (speedup 1.0000x reference)
#include <cuda_runtime.h>
#include <cuda_bf16.h>
#include <cstdint>
#include <math.h>

// Problem constants
#define BB 2
#define SS 4096
#define DD 768
#define HH 12
#define DHH 64
#define DFF 3072
#define MM (BB*SS)    // 8192
#define QKVN (3*DD)   // 2304

// ---------------------------------------------------------------------------
// Scratch (device globals — allocation-free per harness rules)
// ---------------------------------------------------------------------------
__device__ float g_l1[MM*DD];
__device__ float g_qkv[MM*QKVN];     // fused Q|K|V output
__device__ float g_x1[MM*DD];
__device__ float g_l2[MM*DD];
__device__ float g_hb[MM*DFF];
__device__ float g_wqkv[DD*QKVN];    // concat rounded [768][2304]
__device__ float g_bqkv[QKVN];
__device__ float g_w1r[DD*DFF];
__device__ float g_w2r[DFF*DD];

// ---------------------------------------------------------------------------
// Helpers
// ---------------------------------------------------------------------------
__device__ __forceinline__ float f2tf32(float x) {
    unsigned r;
    asm("cvt.rna.tf32.f32 %0, %1;" : "=r"(r) : "f"(x));
    return __uint_as_float(r);
}

__device__ __forceinline__ float ex2(float x) {
    float r;
    asm("ex2.approx.f32 %0, %1;" : "=f"(r) : "f"(x));
    return r;
}

__device__ __forceinline__ uint32_t smem_u32(const void* p) {
    uint32_t a;
    asm("{ .reg .u64 t; cvta.to.shared.u64 t, %1; cvt.u32.u64 %0, t; }"
        : "=r"(a) : "l"(p));
    return a;
}

#define CP_ASYNC16(dst, src) \
    asm volatile("cp.async.cg.shared.global [%0], [%1], 16;" :: "r"((uint32_t)(dst)), "l"(src) : "memory")
#define CP_ASYNC_COMMIT() asm volatile("cp.async.commit_group;" ::: "memory")
#define CP_ASYNC_WAIT(n)  asm volatile("cp.async.wait_group %0;" :: "n"(n) : "memory")

__device__ __forceinline__ void mma_tf32(float (&d)[4],
                                         unsigned a0, unsigned a1, unsigned a2, unsigned a3,
                                         unsigned b0, unsigned b1)
{
    asm volatile(
        "mma.sync.aligned.m16n8k8.row.col.f32.tf32.tf32.f32 "
        "{%0,%1,%2,%3}, {%4,%5,%6,%7}, {%8,%9}, {%0,%1,%2,%3};\n"
        : "+f"(d[0]), "+f"(d[1]), "+f"(d[2]), "+f"(d[3])
        : "r"(a0), "r"(a1), "r"(a2), "r"(a3), "r"(b0), "r"(b1));
}

// ---------------------------------------------------------------------------
// One-pass weight prep: round wq/wk/wv into fused [768][2304], round w1, w2.
// Also concatenates biases (raw copy) into g_bqkv.
// ---------------------------------------------------------------------------
#define DD4  (DD * DD / 4)     // 147456
#define FF4  (DD * DFF / 4)    // 589824
#define TOT4 (3 * DD4 + 2 * FF4)
#define ROW4 (DD / 4)          // 192 float4 per weight row
#define QROW4 (QKVN / 4)       // 576 float4 per fused row

__global__ void prep_kernel(const float* __restrict__ wq, const float* __restrict__ wk,
                            const float* __restrict__ wv, float* __restrict__ wqkv,
                            const float* __restrict__ bq, const float* __restrict__ bk,
                            const float* __restrict__ bv, float* __restrict__ bqkv,
                            const float* __restrict__ w1, float* __restrict__ o1,
                            const float* __restrict__ w2, float* __restrict__ o2)
{
    long i = (long)blockIdx.x * blockDim.x + threadIdx.x;
    if (i >= TOT4) return;

    if (i < QROW4) {   // bias concat (raw fp32; added in fp32 epilogue)
        const float* bsrc = (i < ROW4) ? (bq + i * 4)
                          : (i < 2 * ROW4) ? (bk + (i - ROW4) * 4)
                          : (bv + (i - 2 * ROW4) * 4);
        ((float4*)bqkv)[i] = *(const float4*)bsrc;
    }

    float4 v;
    if (i < 3 * DD4) {
        const int sel   = (int)(i / DD4);          // 0=q,1=k,2=v
        const long loc  = i - (long)sel * DD4;
        const long r    = loc / ROW4;
        const long c4   = loc % ROW4;
        const float4* in = (sel == 0) ? (const float4*)wq
                         : (sel == 1) ? (const float4*)wk : (const float4*)wv;
        v = in[loc];
        ((float4*)wqkv)[r * QROW4 + sel * ROW4 + c4] =
            make_float4(f2tf32(v.x), f2tf32(v.y), f2tf32(v.z), f2tf32(v.w));
    } else if (i < 3 * DD4 + FF4) {
        const long off = i - 3 * DD4;
        v = ((const float4*)w1)[off];
        ((float4*)o1)[off] = make_float4(f2tf32(v.x), f2tf32(v.y), f2tf32(v.z), f2tf32(v.w));
    } else {
        const long off = i - 3 * DD4 - FF4;
        v = ((const float4*)w2)[off];
        ((float4*)o2)[off] = make_float4(f2tf32(v.x), f2tf32(v.y), f2tf32(v.z), f2tf32(v.w));
    }
}

// ---------------------------------------------------------------------------
// LayerNorm: torch-style, unbiased std (ddof=1), normalizer = (sigma + eps).
// 192 threads x float4. Output tf32-rounded.
// ---------------------------------------------------------------------------
__global__ void ln_kernel(const float* __restrict__ x,
                          const float* __restrict__ gamma,
                          const float* __restrict__ beta,
                          float* __restrict__ out)
{
    const int row = blockIdx.x;
    const int tid = threadIdx.x;
    const float* xr = x + (long)row * DD;

    float4 v = *(const float4*)(xr + tid * 4);
    float s  = v.x + v.y + v.z + v.w;
    float ss = v.x * v.x + v.y * v.y + v.z * v.z + v.w * v.w;
#pragma unroll
    for (int o = 16; o > 0; o >>= 1) {
        s  += __shfl_xor_sync(0xffffffffu, s,  o);
        ss += __shfl_xor_sync(0xffffffffu, ss, o);
    }
    __shared__ float sw[6], ssw[6];
    __shared__ float mu_s, inv_s;
    const int warp = tid >> 5, lane = tid & 31;
    if (lane == 0) { sw[warp] = s; ssw[warp] = ss; }
    __syncthreads();
    if (tid == 0) {
        float ts = 0.f, tss = 0.f;
#pragma unroll
        for (int i = 0; i < 6; i++) { ts += sw[i]; tss += ssw[i]; }
        float mu  = ts / 768.f;
        float var = fmaxf((tss - 768.f * mu * mu) / 767.f, 0.f);
        mu_s  = mu;
        inv_s = 1.f / (sqrtf(var) + 1e-6f);
    }
    __syncthreads();
    const float mu = mu_s, inv = inv_s;
    const float4 gm = *(const float4*)(gamma + tid * 4);
    const float4 bt = *(const float4*)(beta + tid * 4);
    *(float4*)(out + (long)row * DD + tid * 4) = make_float4(
        f2tf32(gm.x * (v.x - mu) * inv + bt.x),
        f2tf32(gm.y * (v.y - mu) * inv + bt.y),
        f2tf32(gm.z * (v.z - mu) * inv + bt.z),
        f2tf32(gm.w * (v.w - mu) * inv + bt.w));
}

// ---------------------------------------------------------------------------
// TF32 tensor-core GEMM, 4-stage cp.async pipeline (unchanged from round 7).
// ---------------------------------------------------------------------------
#define AP 20
#define BP 136
#define ASF (128 * AP)
#define BSF (16 * BP)
#define NSTG 4
#define GEMM_SMEM (NSTG * (ASF + BSF) * 4)   // 75776 B

template<int EPI>
__global__ __launch_bounds__(256, 2)
void mma_gemm(const float* __restrict__ A, const float* __restrict__ Bm,
              const float* __restrict__ bias, const float* __restrict__ res,
              float* __restrict__ C, int M, int N, int Kdim)
{
    extern __shared__ float gsm[];
    float* Asm = gsm;
    float* Bsm = gsm + NSTG * ASF;

    const int tid  = threadIdx.x;
    const int wid  = tid >> 5, lane = tid & 31;
    const int wm   = wid >> 2, wn = wid & 3;
    const int g    = lane >> 2, t = lane & 3;
    const int row0 = blockIdx.y * 128, col0 = blockIdx.x * 128;

    const int ar = tid >> 1, ac = (tid & 1) * 8;
    const int br = tid >> 4, bc = (tid & 15) * 8;

    const float* Aptr = A  + (long)(row0 + ar) * Kdim + ac;
    const float* Bptr = Bm + (long)br * N + col0 + bc;

    const uint32_t adst = smem_u32(Asm) + (ar * AP + ac) * 4;
    const uint32_t bdst = smem_u32(Bsm) + (br * BP + bc) * 4;

    float acc[4][4][4];
#pragma unroll
    for (int i = 0; i < 4; i++)
#pragma unroll
        for (int j = 0; j < 4; j++)
#pragma unroll
            for (int k = 0; k < 4; k++) acc[i][j][k] = 0.f;

    const int niter = Kdim / 16;

#pragma unroll
    for (int p = 0; p < 3; p++) {
        const long ka = (long)p * 16;
        const uint32_t ad = adst + p * (ASF * 4);
        const uint32_t bd = bdst + p * (BSF * 4);
        CP_ASYNC16(ad, Aptr + ka);
        CP_ASYNC16(ad + 16, Aptr + ka + 4);
        CP_ASYNC16(bd, Bptr + ka * N);
        CP_ASYNC16(bd + 16, Bptr + ka * N + 4);
        CP_ASYNC_COMMIT();
    }

    for (int it = 0; it < niter; it++) {
        if (it + 2 < niter)      { CP_ASYNC_WAIT(2); }
        else if (it + 1 < niter) { CP_ASYNC_WAIT(1); }
        else                     { CP_ASYNC_WAIT(0); }
        __syncthreads();

        if (it + 3 < niter) {
            const int ns = (it + 3) & (NSTG - 1);
            const long ka = (long)(it + 3) * 16;
            const uint32_t ad = adst + ns * (ASF * 4);
            const uint32_t bd = bdst + ns * (BSF * 4);
            CP_ASYNC16(ad, Aptr + ka);
            CP_ASYNC16(ad + 16, Aptr + ka + 4);
            CP_ASYNC16(bd, Bptr + ka * N);
            CP_ASYNC16(bd + 16, Bptr + ka * N + 4);
            CP_ASYNC_COMMIT();
        }

        const int slot = it & (NSTG - 1);
        const float* as = Asm + slot * ASF;
        const float* bs = Bsm + slot * BSF;
#pragma unroll
        for (int ks = 0; ks < 2; ks++) {
            unsigned af[4][4];
#pragma unroll
            for (int mt = 0; mt < 4; mt++) {
                const int rb = (wm * 64 + mt * 16 + g) * AP + ks * 8 + t;
                af[mt][0] = __float_as_uint(as[rb]);
                af[mt][1] = __float_as_uint(as[rb + 8 * AP]);
                af[mt][2] = __float_as_uint(as[rb + 4]);
                af[mt][3] = __float_as_uint(as[rb + 8 * AP + 4]);
            }
            unsigned bf[4][2];
#pragma unroll
            for (int nt = 0; nt < 4; nt++) {
                const int cb = (ks * 8 + t) * BP + wn * 32 + nt * 8 + g;
                bf[nt][0] = __float_as_uint(bs[cb]);
                bf[nt][1] = __float_as_uint(bs[cb + 4 * BP]);
            }
#pragma unroll
            for (int mt = 0; mt < 4; mt++)
#pragma unroll
                for (int nt = 0; nt < 4; nt++)
                    mma_tf32(acc[mt][nt], af[mt][0], af[mt][1], af[mt][2], af[mt][3],
                             bf[nt][0], bf[nt][1]);
        }
    }

#pragma unroll
    for (int mt = 0; mt < 4; mt++) {
#pragma unroll
        for (int nt = 0; nt < 4; nt++) {
            const int  ccol = col0 + wn * 32 + nt * 8 + 2 * t;
            const long ra   = row0 + wm * 64 + mt * 16 + g;
            const long rb2  = ra + 8;
            const float bx = bias[ccol], by = bias[ccol + 1];
            float v0 = acc[mt][nt][0] + bx;
            float v1 = acc[mt][nt][1] + by;
            float v2 = acc[mt][nt][2] + bx;
            float v3 = acc[mt][nt][3] + by;
            if (EPI == 1) {
                v0 = f2tf32(fmaxf(v0, 0.f)); v1 = f2tf32(fmaxf(v1, 0.f));
                v2 = f2tf32(fmaxf(v2, 0.f)); v3 = f2tf32(fmaxf(v3, 0.f));
            }
            if (EPI == 3) {
                v0 = f2tf32(v0); v1 = f2tf32(v1);
                v2 = f2tf32(v2); v3 = f2tf32(v3);
            }
            if (EPI == 2) {
                const float2 r0 = *(const float2*)(res + ra  * N + ccol);
                const float2 r1 = *(const float2*)(res + rb2 * N + ccol);
                v0 += r0.x; v1 += r0.y; v2 += r1.x; v3 += r1.y;
            }
            *(float2*)(C + ra  * N + ccol) = make_float2(v0, v1);
            *(float2*)(C + rb2 * N + ccol) = make_float2(v2, v3);
        }
    }
}

// ---------------------------------------------------------------------------
// Flash attention, tf32 mma.sync. Q-tile 128 rows, 128 threads = 4 warps,
// warp w owns 32 q-rows (mt=0,1 x 16) -> every K/V B-fragment feeds 2 MMAs.
// Q in registers. K-tile 32, double-buffered (K cp.async, V reg prefetch).
// Vt stores/reads XOR-swizzled -> conflict-free. 2 CTAs/SM (70.7 KB smem).
// Grid x = head (fastest) for mask L2 reuse. Fuses residual: x1 = x + ctx.
// ---------------------------------------------------------------------------
#define PT 68
#define PTV 36
#define QT 128
#define KT 32
// smem: Ks 2x[32][PT] + Vt 2x[64][PTV] + Ps [128][PT]
#define ATTN_SMEM ((2 * KT * PT + 2 * 64 * PTV + QT * PT) * (int)sizeof(float))  // 70656

__global__ __launch_bounds__(128, 2)
void attn_mma_kernel(const float* __restrict__ QKV, const float* __restrict__ mask,
                     const float* __restrict__ x, float* __restrict__ x1)
{
    extern __shared__ float sm[];
    float* KsBase = sm;                              // 2 x [32][PT]
    float* VtBase = sm + 2 * KT * PT;                // 2 x [64 dh][PTV] (transposed, swizzled)
    float* Ps     = sm + 2 * KT * PT + 2 * 64 * PTV; // [128][PT]

    const int tid = threadIdx.x;    // 0..127
    const int w = tid >> 5, lane = tid & 31;
    const int g = lane >> 2, t = lane & 3;
    const int h = blockIdx.x, qb = blockIdx.y, b = blockIdx.z;
    const int q0 = qb * QT, hoff = h * DHH;

    const float* Kp = QKV + DD;        // K block at col 768
    const float* Vp = QKV + 2 * DD;    // V block at col 1536

    const float qscale = 0.125f * 1.4426950408889634f;  // 1/sqrt(64)*log2(e)

    // stage Q through Ps (thread stages row tid -> warp-private rows 32w..32w+31),
    // then pull A-fragments for both 16-row groups into registers.
    unsigned qf[2][8][4];
    {
        const float* qsrc = QKV + ((long)(b * SS + q0 + tid)) * QKVN + hoff;
        float* qdst = &Ps[tid * PT];
#pragma unroll
        for (int i = 0; i < 64; i += 4) {
            float4 v = *(const float4*)(qsrc + i);
            *(float4*)(qdst + i) = make_float4(v.x * qscale, v.y * qscale,
                                               v.z * qscale, v.w * qscale);
        }
        __syncwarp();
#pragma unroll
        for (int mt = 0; mt < 2; mt++)
#pragma unroll
            for (int ks = 0; ks < 8; ks++) {
                const int rb = (w * 32 + mt * 16 + g) * PT + ks * 8 + t;
                qf[mt][ks][0] = __float_as_uint(Ps[rb]);
                qf[mt][ks][1] = __float_as_uint(Ps[rb + 8 * PT]);
                qf[mt][ks][2] = __float_as_uint(Ps[rb + 4]);
                qf[mt][ks][3] = __float_as_uint(Ps[rb + 8 * PT + 4]);
            }
        __syncwarp();
    }

    float o[2][8][4];
#pragma unroll
    for (int mt = 0; mt < 2; mt++)
#pragma unroll
        for (int nt = 0; nt < 8; nt++)
#pragma unroll
            for (int i = 0; i < 4; i++) o[mt][nt][i] = 0.f;
    float m_[2][2], l_[2][2];
#pragma unroll
    for (int mt = 0; mt < 2; mt++) {
        m_[mt][0] = -INFINITY; m_[mt][1] = -INFINITY;
        l_[mt][0] = 0.f;       l_[mt][1] = 0.f;
    }

    const float* mrow[2][2];
#pragma unroll
    for (int mt = 0; mt < 2; mt++) {
        const float* base = mask + ((long)b * SS + q0 + w * 32 + mt * 16 + g) * SS;
        mrow[mt][0] = base;
        mrow[mt][1] = base + 8L * SS;
    }

    // K/V staging mapping: kr = tid>>2 (0..31), cols kc..kc+15
    const int kr = tid >> 2, kc = (tid & 3) * 16;
    const uint32_t ksbase = smem_u32(KsBase);
    const uint32_t ksoff  = (kr * PT + kc) * 4;
    // Vt swizzled key index (constant per thread: dh>>4 == kc>>4 for j<16)
    const int kswz = kr ^ (8 * ((kc >> 4) & 3));

    // prologue: stage kb=0 into slot 0
    float4 vreg[4];
    {
        const long kv = ((long)(b * SS + kr)) * QKVN + hoff + kc;
#pragma unroll
        for (int j = 0; j < 4; j++)
            CP_ASYNC16(ksbase + ksoff + j * 16, Kp + kv + j * 4);
        CP_ASYNC_COMMIT();
#pragma unroll
        for (int j = 0; j < 4; j++)
            vreg[j] = *(const float4*)(Vp + kv + j * 4);
#pragma unroll
        for (int j = 0; j < 4; j++) {
            VtBase[(kc + j * 4 + 0) * PTV + kswz] = vreg[j].x;
            VtBase[(kc + j * 4 + 1) * PTV + kswz] = vreg[j].y;
            VtBase[(kc + j * 4 + 2) * PTV + kswz] = vreg[j].z;
            VtBase[(kc + j * 4 + 3) * PTV + kswz] = vreg[j].w;
        }
        CP_ASYNC_WAIT(0);
    }
    __syncthreads();

    const int NKB = SS / KT;   // 128
    for (int kb = 0; kb < NKB; kb++) {
        const int cur = kb & 1, nxt = cur ^ 1;
        const int k0 = kb * KT;
        const bool more = (kb + 1 < NKB);

        // prefetch next K (cp.async) and next V (registers)
        if (more) {
            const long kv = ((long)(b * SS + k0 + KT + kr)) * QKVN + hoff + kc;
            const uint32_t kd = ksbase + nxt * (KT * PT * 4) + ksoff;
#pragma unroll
            for (int j = 0; j < 4; j++)
                CP_ASYNC16(kd + j * 16, Kp + kv + j * 4);
            CP_ASYNC_COMMIT();
#pragma unroll
            for (int j = 0; j < 4; j++)
                vreg[j] = *(const float4*)(Vp + kv + j * 4);
        }

        const float* Ks = KsBase + cur * KT * PT;
        const float* Vt = VtBase + cur * 64 * PTV;

        // S = Q @ Ks^T : per warp 32 q-rows x 32 keys (B-frag reused x2)
        float s[2][4][4];
#pragma unroll
        for (int mt = 0; mt < 2; mt++)
#pragma unroll
            for (int nt = 0; nt < 4; nt++)
#pragma unroll
                for (int i = 0; i < 4; i++) s[mt][nt][i] = 0.f;
#pragma unroll
        for (int ks = 0; ks < 8; ks++) {
#pragma unroll
            for (int nt = 0; nt < 4; nt++) {
                const int cb = (nt * 8 + g) * PT + ks * 8 + t;
                const unsigned b0 = __float_as_uint(Ks[cb]);
                const unsigned b1 = __float_as_uint(Ks[cb + 4]);
#pragma unroll
                for (int mt = 0; mt < 2; mt++)
                    mma_tf32(s[mt][nt], qf[mt][ks][0], qf[mt][ks][1],
                             qf[mt][ks][2], qf[mt][ks][3], b0, b1);
            }
        }

        // multiplicative mask then streaming softmax (log2 domain)
#pragma unroll
        for (int mt = 0; mt < 2; mt++) {
            float mx_a = -INFINITY, mx_b = -INFINITY;
#pragma unroll
            for (int nt = 0; nt < 4; nt++) {
                const float2 ma = *(const float2*)(mrow[mt][0] + k0 + nt * 8 + 2 * t);
                const float2 mb = *(const float2*)(mrow[mt][1] + k0 + nt * 8 + 2 * t);
                s[mt][nt][0] *= ma.x; s[mt][nt][1] *= ma.y;
                s[mt][nt][2] *= mb.x; s[mt][nt][3] *= mb.y;
                mx_a = fmaxf(mx_a, fmaxf(s[mt][nt][0], s[mt][nt][1]));
                mx_b = fmaxf(mx_b, fmaxf(s[mt][nt][2], s[mt][nt][3]));
            }
            mx_a = fmaxf(mx_a, __shfl_xor_sync(0xffffffffu, mx_a, 1));
            mx_a = fmaxf(mx_a, __shfl_xor_sync(0xffffffffu, mx_a, 2));
            mx_b = fmaxf(mx_b, __shfl_xor_sync(0xffffffffu, mx_b, 1));
            mx_b = fmaxf(mx_b, __shfl_xor_sync(0xffffffffu, mx_b, 2));
            const float mn_a = fmaxf(m_[mt][0], mx_a), mn_b = fmaxf(m_[mt][1], mx_b);
            const float al_a = ex2(m_[mt][0] - mn_a), al_b = ex2(m_[mt][1] - mn_b);
            float sum_a = 0.f, sum_b = 0.f;
#pragma unroll
            for (int nt = 0; nt < 4; nt++) {
                const float p0 = ex2(s[mt][nt][0] - mn_a);
                const float p1 = ex2(s[mt][nt][1] - mn_a);
                const float p2 = ex2(s[mt][nt][2] - mn_b);
                const float p3 = ex2(s[mt][nt][3] - mn_b);
                sum_a += p0 + p1; sum_b += p2 + p3;
                const int pb = (w * 32 + mt * 16 + g) * PT + nt * 8 + 2 * t;
                *(float2*)&Ps[pb] = make_float2(p0, p1);
                *(float2*)&Ps[pb + 8 * PT] = make_float2(p2, p3);
            }
            sum_a += __shfl_xor_sync(0xffffffffu, sum_a, 1);
            sum_a += __shfl_xor_sync(0xffffffffu, sum_a, 2);
            sum_b += __shfl_xor_sync(0xffffffffu, sum_b, 1);
            sum_b += __shfl_xor_sync(0xffffffffu, sum_b, 2);
            l_[mt][0] = l_[mt][0] * al_a + sum_a;
            l_[mt][1] = l_[mt][1] * al_b + sum_b;
            m_[mt][0] = mn_a; m_[mt][1] = mn_b;
#pragma unroll
            for (int nt = 0; nt < 8; nt++) {
                o[mt][nt][0] *= al_a; o[mt][nt][1] *= al_a;
                o[mt][nt][2] *= al_b; o[mt][nt][3] *= al_b;
            }
        }
        __syncwarp();   // Ps rows are warp-private

        // O += P @ V  (32 keys -> 4 MMA k-steps; Vt B-frag reused x2)
#pragma unroll
        for (int ksv = 0; ksv < 4; ksv++) {
            unsigned af[2][4];
#pragma unroll
            for (int mt = 0; mt < 2; mt++) {
                const int rb = (w * 32 + mt * 16 + g) * PT + ksv * 8 + t;
                af[mt][0] = __float_as_uint(Ps[rb]);
                af[mt][1] = __float_as_uint(Ps[rb + 8 * PT]);
                af[mt][2] = __float_as_uint(Ps[rb + 4]);
                af[mt][3] = __float_as_uint(Ps[rb + 8 * PT + 4]);
            }
#pragma unroll
            for (int nt = 0; nt < 8; nt++) {
                const int swz = (nt >> 1) & 3;
                const int cb = (nt * 8 + g) * PTV + 8 * (ksv ^ swz) + t;
                const unsigned b0 = __float_as_uint(Vt[cb]);
                const unsigned b1 = __float_as_uint(Vt[cb + 4]);
#pragma unroll
                for (int mt = 0; mt < 2; mt++)
                    mma_tf32(o[mt][nt], af[mt][0], af[mt][1], af[mt][2], af[mt][3], b0, b1);
            }
        }

        // finish next-stage staging: wait K, write swizzled Vt(nxt)
        if (more) {
            CP_ASYNC_WAIT(0);
            float* vt = VtBase + nxt * 64 * PTV;
#pragma unroll
            for (int j = 0; j < 4; j++) {
                vt[(kc + j * 4 + 0) * PTV + kswz] = vreg[j].x;
                vt[(kc + j * 4 + 1) * PTV + kswz] = vreg[j].y;
                vt[(kc + j * 4 + 2) * PTV + kswz] = vreg[j].z;
                vt[(kc + j * 4 + 3) * PTV + kswz] = vreg[j].w;
            }
        }
        __syncthreads();
    }

    // finalize + fused residual: x1 = x + O / l
#pragma unroll
    for (int mt = 0; mt < 2; mt++) {
        const float inv_a = 1.f / l_[mt][0], inv_b = 1.f / l_[mt][1];
        const long oa = ((long)(b * SS + q0 + w * 32 + mt * 16 + g)) * DD + hoff;
        const long ob = oa + 8L * DD;
#pragma unroll
        for (int nt = 0; nt < 8; nt++) {
            const int c = nt * 8 + 2 * t;
            const float2 xa = *(const float2*)(x + oa + c);
            const float2 xb = *(const float2*)(x + ob + c);
            *(float2*)(x1 + oa + c) = make_float2(xa.x + o[mt][nt][0] * inv_a,
                                                  xa.y + o[mt][nt][1] * inv_a);
            *(float2*)(x1 + ob + c) = make_float2(xb.x + o[mt][nt][2] * inv_b,
                                                  xb.y + o[mt][nt][3] * inv_b);
        }
    }
}

// ---------------------------------------------------------------------------
// Launch
// ---------------------------------------------------------------------------
extern "C" void kernel_launch(void* const* d_in, const int* in_sizes, int n_in,
                              void* d_out, int out_size)
{
    const float* x    = (const float*)d_in[0];
    const float* mask = (const float*)d_in[1];
    const float* wq   = (const float*)d_in[2];
    const float* bq   = (const float*)d_in[3];
    const float* wk   = (const float*)d_in[4];
    const float* bk   = (const float*)d_in[5];
    const float* wv   = (const float*)d_in[6];
    const float* bv   = (const float*)d_in[7];
    // d_in[8]=wo, d_in[9]=bo unused by the reference forward
    const float* w1   = (const float*)d_in[10];
    const float* b1   = (const float*)d_in[11];
    const float* w2   = (const float*)d_in[12];
    const float* b2   = (const float*)d_in[13];
    const float* g1   = (const float*)d_in[14];
    const float* be1  = (const float*)d_in[15];
    const float* g2   = (const float*)d_in[16];
    const float* be2  = (const float*)d_in[17];
    float* out = (float*)d_out;

    float *l1, *qkv, *x1, *l2, *hb, *wqkv, *bqkv, *w1r, *w2r;
    cudaGetSymbolAddress((void**)&l1, g_l1);
    cudaGetSymbolAddress((void**)&qkv, g_qkv);
    cudaGetSymbolAddress((void**)&x1, g_x1);
    cudaGetSymbolAddress((void**)&l2, g_l2);
    cudaGetSymbolAddress((void**)&hb, g_hb);
    cudaGetSymbolAddress((void**)&wqkv, g_wqkv);
    cudaGetSymbolAddress((void**)&bqkv, g_bqkv);
    cudaGetSymbolAddress((void**)&w1r, g_w1r);
    cudaGetSymbolAddress((void**)&w2r, g_w2r);

    cudaFuncSetAttribute(mma_gemm<1>, cudaFuncAttributeMaxDynamicSharedMemorySize, GEMM_SMEM);
    cudaFuncSetAttribute(mma_gemm<2>, cudaFuncAttributeMaxDynamicSharedMemorySize, GEMM_SMEM);
    cudaFuncSetAttribute(mma_gemm<3>, cudaFuncAttributeMaxDynamicSharedMemorySize, GEMM_SMEM);
    cudaFuncSetAttribute(attn_mma_kernel, cudaFuncAttributeMaxDynamicSharedMemorySize, ATTN_SMEM);

    // weight prep: round + concat QKV weights/biases, round w1/w2
    prep_kernel<<<(TOT4 + 255) / 256, 256>>>(wq, wk, wv, wqkv, bq, bk, bv, bqkv,
                                             w1, w1r, w2, w2r);

    // LN1 (rounds output)
    ln_kernel<<<MM, 192>>>(x, g1, be1, l1);

    // Fused QKV projection: [8192,768] @ [768,2304] -> [8192,2304]
    mma_gemm<3><<<dim3(QKVN / 128, MM / 128), 256, GEMM_SMEM>>>(
        l1, wqkv, bqkv, nullptr, qkv, MM, QKVN, DD);

    // Flash attention + residual; head = fastest grid dim for mask L2 reuse
    attn_mma_kernel<<<dim3(HH, SS / QT, BB), 128, ATTN_SMEM>>>(qkv, mask, x, x1);

    // LN2 (rounds output)
    ln_kernel<<<MM, 192>>>(x1, g2, be2, l2);

    // FFN
    mma_gemm<1><<<dim3(DFF / 128, MM / 128), 256, GEMM_SMEM>>>(l2, w1r, b1, nullptr, hb, MM, DFF, DD);
    mma_gemm<2><<<dim3(DD / 128, MM / 128), 256, GEMM_SMEM>>>(hb, w2r, b2, x1, out, MM, DD, DFF);
}

// round 10
// speedup vs baseline: 1.0944x; 1.0944x over previous
#include <cuda_runtime.h>
#include <cuda_bf16.h>
#include <cstdint>
#include <math.h>

// Problem constants
#define BB 2
#define SS 4096
#define DD 768
#define HH 12
#define DHH 64
#define DFF 3072
#define MM (BB*SS)    // 8192
#define QKVN (3*DD)   // 2304

// ---------------------------------------------------------------------------
// Scratch (device globals — allocation-free per harness rules)
// ---------------------------------------------------------------------------
__device__ float g_l1[MM*DD];
__device__ float g_qkv[MM*QKVN];     // fused Q|K|V output
__device__ float g_x1[MM*DD];
__device__ float g_l2[MM*DD];
__device__ float g_hb[MM*DFF];
__device__ float g_wqkv[DD*QKVN];    // concat rounded [768][2304]
__device__ float g_bqkv[QKVN];
__device__ float g_w1r[DD*DFF];
__device__ float g_w2r[DFF*DD];
__device__ __nv_bfloat16 g_vt[(long)BB*HH*DHH*SS];   // V transposed: [b][h][dh][key]

// ---------------------------------------------------------------------------
// Helpers
// ---------------------------------------------------------------------------
__device__ __forceinline__ float f2tf32(float x) {
    unsigned r;
    asm("cvt.rna.tf32.f32 %0, %1;" : "=r"(r) : "f"(x));
    return __uint_as_float(r);
}

__device__ __forceinline__ float ex2(float x) {
    float r;
    asm("ex2.approx.f32 %0, %1;" : "=f"(r) : "f"(x));
    return r;
}

// pack two floats into bf16x2: lo -> bits[15:0], hi -> bits[31:16]
__device__ __forceinline__ unsigned bfpack(float lo, float hi) {
    unsigned r;
    asm("cvt.rn.satfinite.bf16x2.f32 %0, %1, %2;" : "=r"(r) : "f"(hi), "f"(lo));
    return r;
}

__device__ __forceinline__ uint32_t smem_u32(const void* p) {
    uint32_t a;
    asm("{ .reg .u64 t; cvta.to.shared.u64 t, %1; cvt.u32.u64 %0, t; }"
        : "=r"(a) : "l"(p));
    return a;
}

#define CP_ASYNC16(dst, src) \
    asm volatile("cp.async.cg.shared.global [%0], [%1], 16;" :: "r"((uint32_t)(dst)), "l"(src) : "memory")
#define CP_ASYNC_COMMIT() asm volatile("cp.async.commit_group;" ::: "memory")
#define CP_ASYNC_WAIT(n)  asm volatile("cp.async.wait_group %0;" :: "n"(n) : "memory")

__device__ __forceinline__ void mma_tf32(float (&d)[4],
                                         unsigned a0, unsigned a1, unsigned a2, unsigned a3,
                                         unsigned b0, unsigned b1)
{
    asm volatile(
        "mma.sync.aligned.m16n8k8.row.col.f32.tf32.tf32.f32 "
        "{%0,%1,%2,%3}, {%4,%5,%6,%7}, {%8,%9}, {%0,%1,%2,%3};\n"
        : "+f"(d[0]), "+f"(d[1]), "+f"(d[2]), "+f"(d[3])
        : "r"(a0), "r"(a1), "r"(a2), "r"(a3), "r"(b0), "r"(b1));
}

__device__ __forceinline__ void mma_bf16(float (&d)[4],
                                         unsigned a0, unsigned a1, unsigned a2, unsigned a3,
                                         unsigned b0, unsigned b1)
{
    asm volatile(
        "mma.sync.aligned.m16n8k16.row.col.f32.bf16.bf16.f32 "
        "{%0,%1,%2,%3}, {%4,%5,%6,%7}, {%8,%9}, {%0,%1,%2,%3};\n"
        : "+f"(d[0]), "+f"(d[1]), "+f"(d[2]), "+f"(d[3])
        : "r"(a0), "r"(a1), "r"(a2), "r"(a3), "r"(b0), "r"(b1));
}

// ---------------------------------------------------------------------------
// One-pass weight prep: round wq/wk/wv into fused [768][2304], round w1, w2.
// Also concatenates biases (raw copy) into g_bqkv.
// ---------------------------------------------------------------------------
#define DD4  (DD * DD / 4)     // 147456
#define FF4  (DD * DFF / 4)    // 589824
#define TOT4 (3 * DD4 + 2 * FF4)
#define ROW4 (DD / 4)          // 192 float4 per weight row
#define QROW4 (QKVN / 4)       // 576 float4 per fused row

__global__ void prep_kernel(const float* __restrict__ wq, const float* __restrict__ wk,
                            const float* __restrict__ wv, float* __restrict__ wqkv,
                            const float* __restrict__ bq, const float* __restrict__ bk,
                            const float* __restrict__ bv, float* __restrict__ bqkv,
                            const float* __restrict__ w1, float* __restrict__ o1,
                            const float* __restrict__ w2, float* __restrict__ o2)
{
    long i = (long)blockIdx.x * blockDim.x + threadIdx.x;
    if (i >= TOT4) return;

    if (i < QROW4) {   // bias concat (raw fp32; added in fp32 epilogue)
        const float* bsrc = (i < ROW4) ? (bq + i * 4)
                          : (i < 2 * ROW4) ? (bk + (i - ROW4) * 4)
                          : (bv + (i - 2 * ROW4) * 4);
        ((float4*)bqkv)[i] = *(const float4*)bsrc;
    }

    float4 v;
    if (i < 3 * DD4) {
        const int sel   = (int)(i / DD4);          // 0=q,1=k,2=v
        const long loc  = i - (long)sel * DD4;
        const long r    = loc / ROW4;
        const long c4   = loc % ROW4;
        const float4* in = (sel == 0) ? (const float4*)wq
                         : (sel == 1) ? (const float4*)wk : (const float4*)wv;
        v = in[loc];
        ((float4*)wqkv)[r * QROW4 + sel * ROW4 + c4] =
            make_float4(f2tf32(v.x), f2tf32(v.y), f2tf32(v.z), f2tf32(v.w));
    } else if (i < 3 * DD4 + FF4) {
        const long off = i - 3 * DD4;
        v = ((const float4*)w1)[off];
        ((float4*)o1)[off] = make_float4(f2tf32(v.x), f2tf32(v.y), f2tf32(v.z), f2tf32(v.w));
    } else {
        const long off = i - 3 * DD4 - FF4;
        v = ((const float4*)w2)[off];
        ((float4*)o2)[off] = make_float4(f2tf32(v.x), f2tf32(v.y), f2tf32(v.z), f2tf32(v.w));
    }
}

// ---------------------------------------------------------------------------
// V transpose: qkv V block [key][dh] fp32 -> g_vt [b][h][dh][key] bf16.
// Block = 32 keys x 64 dh of one (b,h). 256 threads.
// ---------------------------------------------------------------------------
__global__ void vt_kernel(const float* __restrict__ qkv, __nv_bfloat16* __restrict__ vt)
{
    __shared__ float tile[32][68];
    const int k0 = blockIdx.x * 32;
    const int h  = blockIdx.y, b = blockIdx.z;
    const int t  = threadIdx.x;
    {
        const int key = t >> 3, dc = (t & 7) * 8;
        const float* src = qkv + ((long)(b * SS + k0 + key)) * QKVN + 2 * DD + h * DHH + dc;
        *(float4*)&tile[key][dc]     = *(const float4*)src;
        *(float4*)&tile[key][dc + 4] = *(const float4*)(src + 4);
    }
    __syncthreads();
    {
        const int dh = t >> 2, kc = (t & 3) * 8;
        uint4 ov;
        ov.x = bfpack(tile[kc + 0][dh], tile[kc + 1][dh]);
        ov.y = bfpack(tile[kc + 2][dh], tile[kc + 3][dh]);
        ov.z = bfpack(tile[kc + 4][dh], tile[kc + 5][dh]);
        ov.w = bfpack(tile[kc + 6][dh], tile[kc + 7][dh]);
        *(uint4*)(vt + ((long)((b * HH + h) * DHH + dh)) * SS + k0 + kc) = ov;
    }
}

// ---------------------------------------------------------------------------
// LayerNorm: torch-style, unbiased std (ddof=1), normalizer = (sigma + eps).
// 192 threads x float4. Output tf32-rounded.
// ---------------------------------------------------------------------------
__global__ void ln_kernel(const float* __restrict__ x,
                          const float* __restrict__ gamma,
                          const float* __restrict__ beta,
                          float* __restrict__ out)
{
    const int row = blockIdx.x;
    const int tid = threadIdx.x;
    const float* xr = x + (long)row * DD;

    float4 v = *(const float4*)(xr + tid * 4);
    float s  = v.x + v.y + v.z + v.w;
    float ss = v.x * v.x + v.y * v.y + v.z * v.z + v.w * v.w;
#pragma unroll
    for (int o = 16; o > 0; o >>= 1) {
        s  += __shfl_xor_sync(0xffffffffu, s,  o);
        ss += __shfl_xor_sync(0xffffffffu, ss, o);
    }
    __shared__ float sw[6], ssw[6];
    __shared__ float mu_s, inv_s;
    const int warp = tid >> 5, lane = tid & 31;
    if (lane == 0) { sw[warp] = s; ssw[warp] = ss; }
    __syncthreads();
    if (tid == 0) {
        float ts = 0.f, tss = 0.f;
#pragma unroll
        for (int i = 0; i < 6; i++) { ts += sw[i]; tss += ssw[i]; }
        float mu  = ts / 768.f;
        float var = fmaxf((tss - 768.f * mu * mu) / 767.f, 0.f);
        mu_s  = mu;
        inv_s = 1.f / (sqrtf(var) + 1e-6f);
    }
    __syncthreads();
    const float mu = mu_s, inv = inv_s;
    const float4 gm = *(const float4*)(gamma + tid * 4);
    const float4 bt = *(const float4*)(beta + tid * 4);
    *(float4*)(out + (long)row * DD + tid * 4) = make_float4(
        f2tf32(gm.x * (v.x - mu) * inv + bt.x),
        f2tf32(gm.y * (v.y - mu) * inv + bt.y),
        f2tf32(gm.z * (v.z - mu) * inv + bt.z),
        f2tf32(gm.w * (v.w - mu) * inv + bt.w));
}

// ---------------------------------------------------------------------------
// TF32 tensor-core GEMM, 4-stage cp.async pipeline (unchanged).
// ---------------------------------------------------------------------------
#define AP 20
#define BP 136
#define ASF (128 * AP)
#define BSF (16 * BP)
#define NSTG 4
#define GEMM_SMEM (NSTG * (ASF + BSF) * 4)   // 75776 B

template<int EPI>
__global__ __launch_bounds__(256, 2)
void mma_gemm(const float* __restrict__ A, const float* __restrict__ Bm,
              const float* __restrict__ bias, const float* __restrict__ res,
              float* __restrict__ C, int M, int N, int Kdim)
{
    extern __shared__ float gsm[];
    float* Asm = gsm;
    float* Bsm = gsm + NSTG * ASF;

    const int tid  = threadIdx.x;
    const int wid  = tid >> 5, lane = tid & 31;
    const int wm   = wid >> 2, wn = wid & 3;
    const int g    = lane >> 2, t = lane & 3;
    const int row0 = blockIdx.y * 128, col0 = blockIdx.x * 128;

    const int ar = tid >> 1, ac = (tid & 1) * 8;
    const int br = tid >> 4, bc = (tid & 15) * 8;

    const float* Aptr = A  + (long)(row0 + ar) * Kdim + ac;
    const float* Bptr = Bm + (long)br * N + col0 + bc;

    const uint32_t adst = smem_u32(Asm) + (ar * AP + ac) * 4;
    const uint32_t bdst = smem_u32(Bsm) + (br * BP + bc) * 4;

    float acc[4][4][4];
#pragma unroll
    for (int i = 0; i < 4; i++)
#pragma unroll
        for (int j = 0; j < 4; j++)
#pragma unroll
            for (int k = 0; k < 4; k++) acc[i][j][k] = 0.f;

    const int niter = Kdim / 16;

#pragma unroll
    for (int p = 0; p < 3; p++) {
        const long ka = (long)p * 16;
        const uint32_t ad = adst + p * (ASF * 4);
        const uint32_t bd = bdst + p * (BSF * 4);
        CP_ASYNC16(ad, Aptr + ka);
        CP_ASYNC16(ad + 16, Aptr + ka + 4);
        CP_ASYNC16(bd, Bptr + ka * N);
        CP_ASYNC16(bd + 16, Bptr + ka * N + 4);
        CP_ASYNC_COMMIT();
    }

    for (int it = 0; it < niter; it++) {
        if (it + 2 < niter)      { CP_ASYNC_WAIT(2); }
        else if (it + 1 < niter) { CP_ASYNC_WAIT(1); }
        else                     { CP_ASYNC_WAIT(0); }
        __syncthreads();

        if (it + 3 < niter) {
            const int ns = (it + 3) & (NSTG - 1);
            const long ka = (long)(it + 3) * 16;
            const uint32_t ad = adst + ns * (ASF * 4);
            const uint32_t bd = bdst + ns * (BSF * 4);
            CP_ASYNC16(ad, Aptr + ka);
            CP_ASYNC16(ad + 16, Aptr + ka + 4);
            CP_ASYNC16(bd, Bptr + ka * N);
            CP_ASYNC16(bd + 16, Bptr + ka * N + 4);
            CP_ASYNC_COMMIT();
        }

        const int slot = it & (NSTG - 1);
        const float* as = Asm + slot * ASF;
        const float* bs = Bsm + slot * BSF;
#pragma unroll
        for (int ks = 0; ks < 2; ks++) {
            unsigned af[4][4];
#pragma unroll
            for (int mt = 0; mt < 4; mt++) {
                const int rb = (wm * 64 + mt * 16 + g) * AP + ks * 8 + t;
                af[mt][0] = __float_as_uint(as[rb]);
                af[mt][1] = __float_as_uint(as[rb + 8 * AP]);
                af[mt][2] = __float_as_uint(as[rb + 4]);
                af[mt][3] = __float_as_uint(as[rb + 8 * AP + 4]);
            }
            unsigned bf[4][2];
#pragma unroll
            for (int nt = 0; nt < 4; nt++) {
                const int cb = (ks * 8 + t) * BP + wn * 32 + nt * 8 + g;
                bf[nt][0] = __float_as_uint(bs[cb]);
                bf[nt][1] = __float_as_uint(bs[cb + 4 * BP]);
            }
#pragma unroll
            for (int mt = 0; mt < 4; mt++)
#pragma unroll
                for (int nt = 0; nt < 4; nt++)
                    mma_tf32(acc[mt][nt], af[mt][0], af[mt][1], af[mt][2], af[mt][3],
                             bf[nt][0], bf[nt][1]);
        }
    }

#pragma unroll
    for (int mt = 0; mt < 4; mt++) {
#pragma unroll
        for (int nt = 0; nt < 4; nt++) {
            const int  ccol = col0 + wn * 32 + nt * 8 + 2 * t;
            const long ra   = row0 + wm * 64 + mt * 16 + g;
            const long rb2  = ra + 8;
            const float bx = bias[ccol], by = bias[ccol + 1];
            float v0 = acc[mt][nt][0] + bx;
            float v1 = acc[mt][nt][1] + by;
            float v2 = acc[mt][nt][2] + bx;
            float v3 = acc[mt][nt][3] + by;
            if (EPI == 1) {
                v0 = f2tf32(fmaxf(v0, 0.f)); v1 = f2tf32(fmaxf(v1, 0.f));
                v2 = f2tf32(fmaxf(v2, 0.f)); v3 = f2tf32(fmaxf(v3, 0.f));
            }
            if (EPI == 3) {
                v0 = f2tf32(v0); v1 = f2tf32(v1);
                v2 = f2tf32(v2); v3 = f2tf32(v3);
            }
            if (EPI == 2) {
                const float2 r0 = *(const float2*)(res + ra  * N + ccol);
                const float2 r1 = *(const float2*)(res + rb2 * N + ccol);
                v0 += r0.x; v1 += r0.y; v2 += r1.x; v3 += r1.y;
            }
            *(float2*)(C + ra  * N + ccol) = make_float2(v0, v1);
            *(float2*)(C + rb2 * N + ccol) = make_float2(v2, v3);
        }
    }
}

// ---------------------------------------------------------------------------
// Flash attention. QK^T in tf32 (scores precision), PV in bf16 m16n8k16.
// Q-tile 128 rows, 128 threads = 4 warps, warp w owns 32 q-rows.
// Q in registers. P never touches smem: softmax outputs are packed to
// bf16x2 A-fragments directly in registers (tf32 C-layout == bf16 A-layout).
// K (tf32) and Vt (pre-transposed bf16 [dh][key]) double-buffered via
// cp.async. smem 34.8 KB. Fuses residual: x1 = x + ctx.
// ---------------------------------------------------------------------------
#define PT 68
#define VPW 20                         // Vt pitch (32-bit words per dh row)
#define QT 128
#define KT 32
#define KS_FLOATS (KT * PT)            // 2176 floats per K stage
#define VT_WORDS  (DHH * VPW)          // 1280 words per V stage
#define ATTN_SMEM (QT * PT * 4)        // 34816 B (Q-stage overlays loop bufs)

__global__ __launch_bounds__(128, 2)
void attn_mma_kernel(const float* __restrict__ QKV, const __nv_bfloat16* __restrict__ VT,
                     const float* __restrict__ mask,
                     const float* __restrict__ x, float* __restrict__ x1)
{
    extern __shared__ float sm[];
    float* KsBase = sm;                                  // 2 x [32][PT] floats
    unsigned* VtU = (unsigned*)(sm + 2 * KS_FLOATS);     // 2 x [64][VPW] words

    const int tid = threadIdx.x;    // 0..127
    const int w = tid >> 5, lane = tid & 31;
    const int g = lane >> 2, t = lane & 3;
    const int h = blockIdx.x, qb = blockIdx.y, b = blockIdx.z;
    const int q0 = qb * QT, hoff = h * DHH;

    const float* Kp = QKV + DD;        // K block at col 768

    const float qscale = 0.125f * 1.4426950408889634f;  // 1/sqrt(64)*log2(e)

    // stage Q through sm (thread stages its own warp's row tid), pull
    // A-fragments for both 16-row groups into registers. Warp-private rows ->
    // __syncwarp inside; __syncthreads after, before K/V staging reuses sm.
    unsigned qf[2][8][4];
    {
        const float* qsrc = QKV + ((long)(b * SS + q0 + tid)) * QKVN + hoff;
        float* qdst = &sm[tid * PT];
#pragma unroll
        for (int i = 0; i < 64; i += 4) {
            float4 v = *(const float4*)(qsrc + i);
            *(float4*)(qdst + i) = make_float4(v.x * qscale, v.y * qscale,
                                               v.z * qscale, v.w * qscale);
        }
        __syncwarp();
#pragma unroll
        for (int mt = 0; mt < 2; mt++)
#pragma unroll
            for (int ks = 0; ks < 8; ks++) {
                const int rb = (w * 32 + mt * 16 + g) * PT + ks * 8 + t;
                qf[mt][ks][0] = __float_as_uint(sm[rb]);
                qf[mt][ks][1] = __float_as_uint(sm[rb + 8 * PT]);
                qf[mt][ks][2] = __float_as_uint(sm[rb + 4]);
                qf[mt][ks][3] = __float_as_uint(sm[rb + 8 * PT + 4]);
            }
    }
    __syncthreads();   // protect Q region before K/V staging overwrites it

    float o[2][8][4];
#pragma unroll
    for (int mt = 0; mt < 2; mt++)
#pragma unroll
        for (int nt = 0; nt < 8; nt++)
#pragma unroll
            for (int i = 0; i < 4; i++) o[mt][nt][i] = 0.f;
    float m_[2][2], l_[2][2];
#pragma unroll
    for (int mt = 0; mt < 2; mt++) {
        m_[mt][0] = -INFINITY; m_[mt][1] = -INFINITY;
        l_[mt][0] = 0.f;       l_[mt][1] = 0.f;
    }

    const float* mrow[2][2];
#pragma unroll
    for (int mt = 0; mt < 2; mt++) {
        const float* base = mask + ((long)b * SS + q0 + w * 32 + mt * 16 + g) * SS;
        mrow[mt][0] = base;
        mrow[mt][1] = base + 8L * SS;
    }

    // K staging: kr = tid>>2 (0..31), cols kc..kc+15
    const int kr = tid >> 2, kc = (tid & 3) * 16;
    const uint32_t ksbase = smem_u32(KsBase);
    const uint32_t ksoff  = (kr * PT + kc) * 4;
    // V staging: vrow = tid>>1 (0..63 dh), half = tid&1 (16 keys = 32B each)
    const int vrow = tid >> 1, vhalf = tid & 1;
    const __nv_bfloat16* vbase = VT + ((long)((b * HH + h) * DHH + vrow)) * SS + vhalf * 16;
    const uint32_t vtb = smem_u32(VtU);
    const uint32_t vdoff = (vrow * VPW + vhalf * 8) * 4;

    // prologue: stage kb=0 into slot 0
    {
        const long kv = ((long)(b * SS + kr)) * QKVN + hoff + kc;
#pragma unroll
        for (int j = 0; j < 4; j++)
            CP_ASYNC16(ksbase + ksoff + j * 16, Kp + kv + j * 4);
        CP_ASYNC16(vtb + vdoff,      vbase);
        CP_ASYNC16(vtb + vdoff + 16, vbase + 8);
        CP_ASYNC_COMMIT();
        CP_ASYNC_WAIT(0);
    }
    __syncthreads();

    const int NKB = SS / KT;   // 128
    for (int kb = 0; kb < NKB; kb++) {
        const int cur = kb & 1, nxt = cur ^ 1;
        const int k0 = kb * KT;
        const bool more = (kb + 1 < NKB);

        // prefetch next K and Vt tiles (cp.async)
        if (more) {
            const long kv = ((long)(b * SS + k0 + KT + kr)) * QKVN + hoff + kc;
            const uint32_t kd = ksbase + nxt * (KS_FLOATS * 4) + ksoff;
#pragma unroll
            for (int j = 0; j < 4; j++)
                CP_ASYNC16(kd + j * 16, Kp + kv + j * 4);
            const uint32_t vd = vtb + nxt * (VT_WORDS * 4) + vdoff;
            CP_ASYNC16(vd,      vbase + k0 + KT);
            CP_ASYNC16(vd + 16, vbase + k0 + KT + 8);
            CP_ASYNC_COMMIT();
        }

        const float* Ks = KsBase + cur * KS_FLOATS;
        const unsigned* Vt = VtU + cur * VT_WORDS;

        // S = Q @ Ks^T : per warp 32 q-rows x 32 keys (tf32)
        float s[2][4][4];
#pragma unroll
        for (int mt = 0; mt < 2; mt++)
#pragma unroll
            for (int nt = 0; nt < 4; nt++)
#pragma unroll
                for (int i = 0; i < 4; i++) s[mt][nt][i] = 0.f;
#pragma unroll
        for (int ks = 0; ks < 8; ks++) {
#pragma unroll
            for (int nt = 0; nt < 4; nt++) {
                const int cb = (nt * 8 + g) * PT + ks * 8 + t;
                const unsigned b0 = __float_as_uint(Ks[cb]);
                const unsigned b1 = __float_as_uint(Ks[cb + 4]);
#pragma unroll
                for (int mt = 0; mt < 2; mt++)
                    mma_tf32(s[mt][nt], qf[mt][ks][0], qf[mt][ks][1],
                             qf[mt][ks][2], qf[mt][ks][3], b0, b1);
            }
        }

        // multiplicative mask then streaming softmax (log2 domain); p -> s
#pragma unroll
        for (int mt = 0; mt < 2; mt++) {
            float mx_a = -INFINITY, mx_b = -INFINITY;
#pragma unroll
            for (int nt = 0; nt < 4; nt++) {
                const float2 ma = *(const float2*)(mrow[mt][0] + k0 + nt * 8 + 2 * t);
                const float2 mb = *(const float2*)(mrow[mt][1] + k0 + nt * 8 + 2 * t);
                s[mt][nt][0] *= ma.x; s[mt][nt][1] *= ma.y;
                s[mt][nt][2] *= mb.x; s[mt][nt][3] *= mb.y;
                mx_a = fmaxf(mx_a, fmaxf(s[mt][nt][0], s[mt][nt][1]));
                mx_b = fmaxf(mx_b, fmaxf(s[mt][nt][2], s[mt][nt][3]));
            }
            mx_a = fmaxf(mx_a, __shfl_xor_sync(0xffffffffu, mx_a, 1));
            mx_a = fmaxf(mx_a, __shfl_xor_sync(0xffffffffu, mx_a, 2));
            mx_b = fmaxf(mx_b, __shfl_xor_sync(0xffffffffu, mx_b, 1));
            mx_b = fmaxf(mx_b, __shfl_xor_sync(0xffffffffu, mx_b, 2));
            const float mn_a = fmaxf(m_[mt][0], mx_a), mn_b = fmaxf(m_[mt][1], mx_b);
            const float al_a = ex2(m_[mt][0] - mn_a), al_b = ex2(m_[mt][1] - mn_b);
            float sum_a = 0.f, sum_b = 0.f;
#pragma unroll
            for (int nt = 0; nt < 4; nt++) {
                s[mt][nt][0] = ex2(s[mt][nt][0] - mn_a);
                s[mt][nt][1] = ex2(s[mt][nt][1] - mn_a);
                s[mt][nt][2] = ex2(s[mt][nt][2] - mn_b);
                s[mt][nt][3] = ex2(s[mt][nt][3] - mn_b);
                sum_a += s[mt][nt][0] + s[mt][nt][1];
                sum_b += s[mt][nt][2] + s[mt][nt][3];
            }
            sum_a += __shfl_xor_sync(0xffffffffu, sum_a, 1);
            sum_a += __shfl_xor_sync(0xffffffffu, sum_a, 2);
            sum_b += __shfl_xor_sync(0xffffffffu, sum_b, 1);
            sum_b += __shfl_xor_sync(0xffffffffu, sum_b, 2);
            l_[mt][0] = l_[mt][0] * al_a + sum_a;
            l_[mt][1] = l_[mt][1] * al_b + sum_b;
            m_[mt][0] = mn_a; m_[mt][1] = mn_b;
#pragma unroll
            for (int nt = 0; nt < 8; nt++) {
                o[mt][nt][0] *= al_a; o[mt][nt][1] *= al_a;
                o[mt][nt][2] *= al_b; o[mt][nt][3] *= al_b;
            }
        }

        // O += P @ V in bf16 m16n8k16. P A-frags packed from registers:
        // tf32 C-layout of S == bf16 A-layout (rows g/g+8, k = keys 2t,2t+1,+8).
#pragma unroll
        for (int kstep = 0; kstep < 2; kstep++) {
            unsigned a[2][4];
#pragma unroll
            for (int mt = 0; mt < 2; mt++) {
                const int n0 = kstep * 2, n1 = n0 + 1;
                a[mt][0] = bfpack(s[mt][n0][0], s[mt][n0][1]);
                a[mt][1] = bfpack(s[mt][n0][2], s[mt][n0][3]);
                a[mt][2] = bfpack(s[mt][n1][0], s[mt][n1][1]);
                a[mt][3] = bfpack(s[mt][n1][2], s[mt][n1][3]);
            }
#pragma unroll
            for (int nt = 0; nt < 8; nt++) {
                const int wi = (nt * 8 + g) * VPW + kstep * 8 + t;
                const unsigned b0 = Vt[wi];
                const unsigned b1 = Vt[wi + 4];
#pragma unroll
                for (int mt = 0; mt < 2; mt++)
                    mma_bf16(o[mt][nt], a[mt][0], a[mt][1], a[mt][2], a[mt][3], b0, b1);
            }
        }

        CP_ASYNC_WAIT(0);
        __syncthreads();
    }

    // finalize + fused residual: x1 = x + O / l
#pragma unroll
    for (int mt = 0; mt < 2; mt++) {
        const float inv_a = 1.f / l_[mt][0], inv_b = 1.f / l_[mt][1];
        const long oa = ((long)(b * SS + q0 + w * 32 + mt * 16 + g)) * DD + hoff;
        const long ob = oa + 8L * DD;
#pragma unroll
        for (int nt = 0; nt < 8; nt++) {
            const int c = nt * 8 + 2 * t;
            const float2 xa = *(const float2*)(x + oa + c);
            const float2 xb = *(const float2*)(x + ob + c);
            *(float2*)(x1 + oa + c) = make_float2(xa.x + o[mt][nt][0] * inv_a,
                                                  xa.y + o[mt][nt][1] * inv_a);
            *(float2*)(x1 + ob + c) = make_float2(xb.x + o[mt][nt][2] * inv_b,
                                                  xb.y + o[mt][nt][3] * inv_b);
        }
    }
}

// ---------------------------------------------------------------------------
// Launch
// ---------------------------------------------------------------------------
extern "C" void kernel_launch(void* const* d_in, const int* in_sizes, int n_in,
                              void* d_out, int out_size)
{
    const float* x    = (const float*)d_in[0];
    const float* mask = (const float*)d_in[1];
    const float* wq   = (const float*)d_in[2];
    const float* bq   = (const float*)d_in[3];
    const float* wk   = (const float*)d_in[4];
    const float* bk   = (const float*)d_in[5];
    const float* wv   = (const float*)d_in[6];
    const float* bv   = (const float*)d_in[7];
    // d_in[8]=wo, d_in[9]=bo unused by the reference forward
    const float* w1   = (const float*)d_in[10];
    const float* b1   = (const float*)d_in[11];
    const float* w2   = (const float*)d_in[12];
    const float* b2   = (const float*)d_in[13];
    const float* g1   = (const float*)d_in[14];
    const float* be1  = (const float*)d_in[15];
    const float* g2   = (const float*)d_in[16];
    const float* be2  = (const float*)d_in[17];
    float* out = (float*)d_out;

    float *l1, *qkv, *x1, *l2, *hb, *wqkv, *bqkv, *w1r, *w2r;
    __nv_bfloat16* vt;
    cudaGetSymbolAddress((void**)&l1, g_l1);
    cudaGetSymbolAddress((void**)&qkv, g_qkv);
    cudaGetSymbolAddress((void**)&x1, g_x1);
    cudaGetSymbolAddress((void**)&l2, g_l2);
    cudaGetSymbolAddress((void**)&hb, g_hb);
    cudaGetSymbolAddress((void**)&wqkv, g_wqkv);
    cudaGetSymbolAddress((void**)&bqkv, g_bqkv);
    cudaGetSymbolAddress((void**)&w1r, g_w1r);
    cudaGetSymbolAddress((void**)&w2r, g_w2r);
    cudaGetSymbolAddress((void**)&vt, g_vt);

    cudaFuncSetAttribute(mma_gemm<1>, cudaFuncAttributeMaxDynamicSharedMemorySize, GEMM_SMEM);
    cudaFuncSetAttribute(mma_gemm<2>, cudaFuncAttributeMaxDynamicSharedMemorySize, GEMM_SMEM);
    cudaFuncSetAttribute(mma_gemm<3>, cudaFuncAttributeMaxDynamicSharedMemorySize, GEMM_SMEM);
    cudaFuncSetAttribute(attn_mma_kernel, cudaFuncAttributeMaxDynamicSharedMemorySize, ATTN_SMEM);

    // weight prep: round + concat QKV weights/biases, round w1/w2
    prep_kernel<<<(TOT4 + 255) / 256, 256>>>(wq, wk, wv, wqkv, bq, bk, bv, bqkv,
                                             w1, w1r, w2, w2r);

    // LN1 (rounds output)
    ln_kernel<<<MM, 192>>>(x, g1, be1, l1);

    // Fused QKV projection: [8192,768] @ [768,2304] -> [8192,2304]
    mma_gemm<3><<<dim3(QKVN / 128, MM / 128), 256, GEMM_SMEM>>>(
        l1, wqkv, bqkv, nullptr, qkv, MM, QKVN, DD);

    // V -> transposed bf16 [b][h][dh][key]
    vt_kernel<<<dim3(SS / 32, HH, BB), 256>>>(qkv, vt);

    // Flash attention + residual; head = fastest grid dim for mask L2 reuse
    attn_mma_kernel<<<dim3(HH, SS / QT, BB), 128, ATTN_SMEM>>>(qkv, vt, mask, x, x1);

    // LN2 (rounds output)
    ln_kernel<<<MM, 192>>>(x1, g2, be2, l2);

    // FFN
    mma_gemm<1><<<dim3(DFF / 128, MM / 128), 256, GEMM_SMEM>>>(l2, w1r, b1, nullptr, hb, MM, DFF, DD);
    mma_gemm<2><<<dim3(DD / 128, MM / 128), 256, GEMM_SMEM>>>(hb, w2r, b2, x1, out, MM, DD, DFF);
}

// round 11
// speedup vs baseline: 1.2532x; 1.1452x over previous
#include <cuda_runtime.h>
#include <cuda_bf16.h>
#include <cstdint>
#include <math.h>

// Problem constants
#define BB 2
#define SS 4096
#define DD 768
#define HH 12
#define DHH 64
#define DFF 3072
#define MM (BB*SS)    // 8192
#define QKVN (3*DD)   // 2304

// ---------------------------------------------------------------------------
// Scratch (device globals — allocation-free per harness rules)
// ---------------------------------------------------------------------------
__device__ float g_l1[MM*DD];
__device__ float g_qkv[MM*QKVN];     // fused Q|K|V output
__device__ float g_x1[MM*DD];
__device__ float g_l2[MM*DD];
__device__ float g_hb[MM*DFF];
__device__ float g_wqkv[DD*QKVN];    // concat rounded [768][2304]
__device__ float g_bqkv[QKVN];
__device__ float g_w1r[DD*DFF];
__device__ float g_w2r[DFF*DD];
__device__ __nv_bfloat16 g_vt[(long)BB*HH*DHH*SS];   // V transposed: [b][h][dh][key]
__device__ __nv_bfloat16 g_kb[(long)BB*HH*SS*DHH];   // K bf16: [b][h][key][dh]

// ---------------------------------------------------------------------------
// Helpers
// ---------------------------------------------------------------------------
__device__ __forceinline__ float f2tf32(float x) {
    unsigned r;
    asm("cvt.rna.tf32.f32 %0, %1;" : "=r"(r) : "f"(x));
    return __uint_as_float(r);
}

__device__ __forceinline__ float ex2(float x) {
    float r;
    asm("ex2.approx.f32 %0, %1;" : "=f"(r) : "f"(x));
    return r;
}

// pack two floats into bf16x2: lo -> bits[15:0], hi -> bits[31:16]
__device__ __forceinline__ unsigned bfpack(float lo, float hi) {
    unsigned r;
    asm("cvt.rn.satfinite.bf16x2.f32 %0, %1, %2;" : "=r"(r) : "f"(hi), "f"(lo));
    return r;
}

__device__ __forceinline__ uint32_t smem_u32(const void* p) {
    uint32_t a;
    asm("{ .reg .u64 t; cvta.to.shared.u64 t, %1; cvt.u32.u64 %0, t; }"
        : "=r"(a) : "l"(p));
    return a;
}

#define CP_ASYNC16(dst, src) \
    asm volatile("cp.async.cg.shared.global [%0], [%1], 16;" :: "r"((uint32_t)(dst)), "l"(src) : "memory")
#define CP_ASYNC_COMMIT() asm volatile("cp.async.commit_group;" ::: "memory")
#define CP_ASYNC_WAIT(n)  asm volatile("cp.async.wait_group %0;" :: "n"(n) : "memory")

__device__ __forceinline__ void mma_tf32(float (&d)[4],
                                         unsigned a0, unsigned a1, unsigned a2, unsigned a3,
                                         unsigned b0, unsigned b1)
{
    asm volatile(
        "mma.sync.aligned.m16n8k8.row.col.f32.tf32.tf32.f32 "
        "{%0,%1,%2,%3}, {%4,%5,%6,%7}, {%8,%9}, {%0,%1,%2,%3};\n"
        : "+f"(d[0]), "+f"(d[1]), "+f"(d[2]), "+f"(d[3])
        : "r"(a0), "r"(a1), "r"(a2), "r"(a3), "r"(b0), "r"(b1));
}

__device__ __forceinline__ void mma_bf16(float (&d)[4],
                                         unsigned a0, unsigned a1, unsigned a2, unsigned a3,
                                         unsigned b0, unsigned b1)
{
    asm volatile(
        "mma.sync.aligned.m16n8k16.row.col.f32.bf16.bf16.f32 "
        "{%0,%1,%2,%3}, {%4,%5,%6,%7}, {%8,%9}, {%0,%1,%2,%3};\n"
        : "+f"(d[0]), "+f"(d[1]), "+f"(d[2]), "+f"(d[3])
        : "r"(a0), "r"(a1), "r"(a2), "r"(a3), "r"(b0), "r"(b1));
}

// ---------------------------------------------------------------------------
// One-pass weight prep: round wq/wk/wv into fused [768][2304], round w1, w2.
// Also concatenates biases (raw copy) into g_bqkv.
// ---------------------------------------------------------------------------
#define DD4  (DD * DD / 4)     // 147456
#define FF4  (DD * DFF / 4)    // 589824
#define TOT4 (3 * DD4 + 2 * FF4)
#define ROW4 (DD / 4)          // 192 float4 per weight row
#define QROW4 (QKVN / 4)       // 576 float4 per fused row

__global__ void prep_kernel(const float* __restrict__ wq, const float* __restrict__ wk,
                            const float* __restrict__ wv, float* __restrict__ wqkv,
                            const float* __restrict__ bq, const float* __restrict__ bk,
                            const float* __restrict__ bv, float* __restrict__ bqkv,
                            const float* __restrict__ w1, float* __restrict__ o1,
                            const float* __restrict__ w2, float* __restrict__ o2)
{
    long i = (long)blockIdx.x * blockDim.x + threadIdx.x;
    if (i >= TOT4) return;

    if (i < QROW4) {   // bias concat (raw fp32; added in fp32 epilogue)
        const float* bsrc = (i < ROW4) ? (bq + i * 4)
                          : (i < 2 * ROW4) ? (bk + (i - ROW4) * 4)
                          : (bv + (i - 2 * ROW4) * 4);
        ((float4*)bqkv)[i] = *(const float4*)bsrc;
    }

    float4 v;
    if (i < 3 * DD4) {
        const int sel   = (int)(i / DD4);          // 0=q,1=k,2=v
        const long loc  = i - (long)sel * DD4;
        const long r    = loc / ROW4;
        const long c4   = loc % ROW4;
        const float4* in = (sel == 0) ? (const float4*)wq
                         : (sel == 1) ? (const float4*)wk : (const float4*)wv;
        v = in[loc];
        ((float4*)wqkv)[r * QROW4 + sel * ROW4 + c4] =
            make_float4(f2tf32(v.x), f2tf32(v.y), f2tf32(v.z), f2tf32(v.w));
    } else if (i < 3 * DD4 + FF4) {
        const long off = i - 3 * DD4;
        v = ((const float4*)w1)[off];
        ((float4*)o1)[off] = make_float4(f2tf32(v.x), f2tf32(v.y), f2tf32(v.z), f2tf32(v.w));
    } else {
        const long off = i - 3 * DD4 - FF4;
        v = ((const float4*)w2)[off];
        ((float4*)o2)[off] = make_float4(f2tf32(v.x), f2tf32(v.y), f2tf32(v.z), f2tf32(v.w));
    }
}

// ---------------------------------------------------------------------------
// K/V bf16 prep: V -> g_vt [b][h][dh][key] (transposed), K -> g_kb
// [b][h][key][dh] (straight convert). Block = 32 keys x 64 dh of one (b,h).
// ---------------------------------------------------------------------------
__global__ void kv_kernel(const float* __restrict__ qkv,
                          __nv_bfloat16* __restrict__ vt,
                          __nv_bfloat16* __restrict__ kb)
{
    __shared__ float tile[32][68];
    const int k0 = blockIdx.x * 32;
    const int h  = blockIdx.y, b = blockIdx.z;
    const int t  = threadIdx.x;
    {
        const int key = t >> 3, dc = (t & 7) * 8;
        const float* src = qkv + ((long)(b * SS + k0 + key)) * QKVN + 2 * DD + h * DHH + dc;
        *(float4*)&tile[key][dc]     = *(const float4*)src;
        *(float4*)&tile[key][dc + 4] = *(const float4*)(src + 4);
        // K convert (no transpose): 8 fp32 -> 8 bf16
        const float* ksrc = qkv + ((long)(b * SS + k0 + key)) * QKVN + DD + h * DHH + dc;
        float4 ka = *(const float4*)ksrc;
        float4 kbv = *(const float4*)(ksrc + 4);
        uint4 kw;
        kw.x = bfpack(ka.x, ka.y);  kw.y = bfpack(ka.z, ka.w);
        kw.z = bfpack(kbv.x, kbv.y); kw.w = bfpack(kbv.z, kbv.w);
        *(uint4*)(kb + ((long)((b * HH + h) * SS + k0 + key)) * DHH + dc) = kw;
    }
    __syncthreads();
    {
        const int dh = t >> 2, kc = (t & 3) * 8;
        uint4 ov;
        ov.x = bfpack(tile[kc + 0][dh], tile[kc + 1][dh]);
        ov.y = bfpack(tile[kc + 2][dh], tile[kc + 3][dh]);
        ov.z = bfpack(tile[kc + 4][dh], tile[kc + 5][dh]);
        ov.w = bfpack(tile[kc + 6][dh], tile[kc + 7][dh]);
        *(uint4*)(vt + ((long)((b * HH + h) * DHH + dh)) * SS + k0 + kc) = ov;
    }
}

// ---------------------------------------------------------------------------
// LayerNorm: torch-style, unbiased std (ddof=1), normalizer = (sigma + eps).
// 192 threads x float4. Output tf32-rounded.
// ---------------------------------------------------------------------------
__global__ void ln_kernel(const float* __restrict__ x,
                          const float* __restrict__ gamma,
                          const float* __restrict__ beta,
                          float* __restrict__ out)
{
    const int row = blockIdx.x;
    const int tid = threadIdx.x;
    const float* xr = x + (long)row * DD;

    float4 v = *(const float4*)(xr + tid * 4);
    float s  = v.x + v.y + v.z + v.w;
    float ss = v.x * v.x + v.y * v.y + v.z * v.z + v.w * v.w;
#pragma unroll
    for (int o = 16; o > 0; o >>= 1) {
        s  += __shfl_xor_sync(0xffffffffu, s,  o);
        ss += __shfl_xor_sync(0xffffffffu, ss, o);
    }
    __shared__ float sw[6], ssw[6];
    __shared__ float mu_s, inv_s;
    const int warp = tid >> 5, lane = tid & 31;
    if (lane == 0) { sw[warp] = s; ssw[warp] = ss; }
    __syncthreads();
    if (tid == 0) {
        float ts = 0.f, tss = 0.f;
#pragma unroll
        for (int i = 0; i < 6; i++) { ts += sw[i]; tss += ssw[i]; }
        float mu  = ts / 768.f;
        float var = fmaxf((tss - 768.f * mu * mu) / 767.f, 0.f);
        mu_s  = mu;
        inv_s = 1.f / (sqrtf(var) + 1e-6f);
    }
    __syncthreads();
    const float mu = mu_s, inv = inv_s;
    const float4 gm = *(const float4*)(gamma + tid * 4);
    const float4 bt = *(const float4*)(beta + tid * 4);
    *(float4*)(out + (long)row * DD + tid * 4) = make_float4(
        f2tf32(gm.x * (v.x - mu) * inv + bt.x),
        f2tf32(gm.y * (v.y - mu) * inv + bt.y),
        f2tf32(gm.z * (v.z - mu) * inv + bt.z),
        f2tf32(gm.w * (v.w - mu) * inv + bt.w));
}

// ---------------------------------------------------------------------------
// TF32 tensor-core GEMM, 4-stage cp.async pipeline (unchanged).
// ---------------------------------------------------------------------------
#define AP 20
#define BP 136
#define ASF (128 * AP)
#define BSF (16 * BP)
#define NSTG 4
#define GEMM_SMEM (NSTG * (ASF + BSF) * 4)   // 75776 B

template<int EPI>
__global__ __launch_bounds__(256, 2)
void mma_gemm(const float* __restrict__ A, const float* __restrict__ Bm,
              const float* __restrict__ bias, const float* __restrict__ res,
              float* __restrict__ C, int M, int N, int Kdim)
{
    extern __shared__ float gsm[];
    float* Asm = gsm;
    float* Bsm = gsm + NSTG * ASF;

    const int tid  = threadIdx.x;
    const int wid  = tid >> 5, lane = tid & 31;
    const int wm   = wid >> 2, wn = wid & 3;
    const int g    = lane >> 2, t = lane & 3;
    const int row0 = blockIdx.y * 128, col0 = blockIdx.x * 128;

    const int ar = tid >> 1, ac = (tid & 1) * 8;
    const int br = tid >> 4, bc = (tid & 15) * 8;

    const float* Aptr = A  + (long)(row0 + ar) * Kdim + ac;
    const float* Bptr = Bm + (long)br * N + col0 + bc;

    const uint32_t adst = smem_u32(Asm) + (ar * AP + ac) * 4;
    const uint32_t bdst = smem_u32(Bsm) + (br * BP + bc) * 4;

    float acc[4][4][4];
#pragma unroll
    for (int i = 0; i < 4; i++)
#pragma unroll
        for (int j = 0; j < 4; j++)
#pragma unroll
            for (int k = 0; k < 4; k++) acc[i][j][k] = 0.f;

    const int niter = Kdim / 16;

#pragma unroll
    for (int p = 0; p < 3; p++) {
        const long ka = (long)p * 16;
        const uint32_t ad = adst + p * (ASF * 4);
        const uint32_t bd = bdst + p * (BSF * 4);
        CP_ASYNC16(ad, Aptr + ka);
        CP_ASYNC16(ad + 16, Aptr + ka + 4);
        CP_ASYNC16(bd, Bptr + ka * N);
        CP_ASYNC16(bd + 16, Bptr + ka * N + 4);
        CP_ASYNC_COMMIT();
    }

    for (int it = 0; it < niter; it++) {
        if (it + 2 < niter)      { CP_ASYNC_WAIT(2); }
        else if (it + 1 < niter) { CP_ASYNC_WAIT(1); }
        else                     { CP_ASYNC_WAIT(0); }
        __syncthreads();

        if (it + 3 < niter) {
            const int ns = (it + 3) & (NSTG - 1);
            const long ka = (long)(it + 3) * 16;
            const uint32_t ad = adst + ns * (ASF * 4);
            const uint32_t bd = bdst + ns * (BSF * 4);
            CP_ASYNC16(ad, Aptr + ka);
            CP_ASYNC16(ad + 16, Aptr + ka + 4);
            CP_ASYNC16(bd, Bptr + ka * N);
            CP_ASYNC16(bd + 16, Bptr + ka * N + 4);
            CP_ASYNC_COMMIT();
        }

        const int slot = it & (NSTG - 1);
        const float* as = Asm + slot * ASF;
        const float* bs = Bsm + slot * BSF;
#pragma unroll
        for (int ks = 0; ks < 2; ks++) {
            unsigned af[4][4];
#pragma unroll
            for (int mt = 0; mt < 4; mt++) {
                const int rb = (wm * 64 + mt * 16 + g) * AP + ks * 8 + t;
                af[mt][0] = __float_as_uint(as[rb]);
                af[mt][1] = __float_as_uint(as[rb + 8 * AP]);
                af[mt][2] = __float_as_uint(as[rb + 4]);
                af[mt][3] = __float_as_uint(as[rb + 8 * AP + 4]);
            }
            unsigned bf[4][2];
#pragma unroll
            for (int nt = 0; nt < 4; nt++) {
                const int cb = (ks * 8 + t) * BP + wn * 32 + nt * 8 + g;
                bf[nt][0] = __float_as_uint(bs[cb]);
                bf[nt][1] = __float_as_uint(bs[cb + 4 * BP]);
            }
#pragma unroll
            for (int mt = 0; mt < 4; mt++)
#pragma unroll
                for (int nt = 0; nt < 4; nt++)
                    mma_tf32(acc[mt][nt], af[mt][0], af[mt][1], af[mt][2], af[mt][3],
                             bf[nt][0], bf[nt][1]);
        }
    }

#pragma unroll
    for (int mt = 0; mt < 4; mt++) {
#pragma unroll
        for (int nt = 0; nt < 4; nt++) {
            const int  ccol = col0 + wn * 32 + nt * 8 + 2 * t;
            const long ra   = row0 + wm * 64 + mt * 16 + g;
            const long rb2  = ra + 8;
            const float bx = bias[ccol], by = bias[ccol + 1];
            float v0 = acc[mt][nt][0] + bx;
            float v1 = acc[mt][nt][1] + by;
            float v2 = acc[mt][nt][2] + bx;
            float v3 = acc[mt][nt][3] + by;
            if (EPI == 1) {
                v0 = f2tf32(fmaxf(v0, 0.f)); v1 = f2tf32(fmaxf(v1, 0.f));
                v2 = f2tf32(fmaxf(v2, 0.f)); v3 = f2tf32(fmaxf(v3, 0.f));
            }
            if (EPI == 3) {
                v0 = f2tf32(v0); v1 = f2tf32(v1);
                v2 = f2tf32(v2); v3 = f2tf32(v3);
            }
            if (EPI == 2) {
                const float2 r0 = *(const float2*)(res + ra  * N + ccol);
                const float2 r1 = *(const float2*)(res + rb2 * N + ccol);
                v0 += r0.x; v1 += r0.y; v2 += r1.x; v3 += r1.y;
            }
            *(float2*)(C + ra  * N + ccol) = make_float2(v0, v1);
            *(float2*)(C + rb2 * N + ccol) = make_float2(v2, v3);
        }
    }
}

// ---------------------------------------------------------------------------
// Flash attention, all-bf16 tensor path. QK^T and PV both m16n8k16 bf16;
// fp32 softmax state. Q-tile 128 rows, 128 threads = 4 warps, warp w owns
// 32 q-rows. Q packed bf16x2 in registers; P packed in registers (no smem);
// K (bf16 [key][dh]) and Vt (bf16 [dh][key]) double-buffered via cp.async.
// smem 19.5 KB. Fuses residual: x1 = x + ctx.
// ---------------------------------------------------------------------------
#define QPW 36                         // packed Q pitch (words): banks 4g+t
#define KPW 36                         // K stage pitch (words)
#define VPW 20                         // Vt stage pitch (words)
#define QT 128
#define KT 32
#define KSW (KT * KPW)                 // 1152 words per K stage
#define VTW (DHH * VPW)                // 1280 words per V stage
#define ATTN_SMEM ((2 * KSW + 2 * VTW) * 4)   // 19456 B (Q overlay fits: 128*36=4608 words)

__global__ __launch_bounds__(128, 2)
void attn_mma_kernel(const float* __restrict__ QKV,
                     const __nv_bfloat16* __restrict__ KB,
                     const __nv_bfloat16* __restrict__ VT,
                     const float* __restrict__ mask,
                     const float* __restrict__ x, float* __restrict__ x1)
{
    extern __shared__ float sm[];
    unsigned* KsU = (unsigned*)sm;            // 2 x [32][KPW]
    unsigned* VtU = (unsigned*)sm + 2 * KSW;  // 2 x [64][VPW]

    const int tid = threadIdx.x;    // 0..127
    const int w = tid >> 5, lane = tid & 31;
    const int g = lane >> 2, t = lane & 3;
    const int h = blockIdx.x, qb = blockIdx.y, b = blockIdx.z;
    const int q0 = qb * QT, hoff = h * DHH;

    const float qscale = 0.125f * 1.4426950408889634f;  // 1/sqrt(64)*log2(e)

    // stage Q packed bf16x2 (scale folded) through smem, pull A-frags to regs.
    unsigned qf[2][4][4];
    {
        unsigned* qw = (unsigned*)sm;
        const float* qsrc = QKV + ((long)(b * SS + q0 + tid)) * QKVN + hoff;
#pragma unroll
        for (int i = 0; i < 8; i++) {
            float4 a = *(const float4*)(qsrc + i * 8);
            float4 c = *(const float4*)(qsrc + i * 8 + 4);
            uint4 pw;
            pw.x = bfpack(a.x * qscale, a.y * qscale);
            pw.y = bfpack(a.z * qscale, a.w * qscale);
            pw.z = bfpack(c.x * qscale, c.y * qscale);
            pw.w = bfpack(c.z * qscale, c.w * qscale);
            *(uint4*)&qw[tid * QPW + i * 4] = pw;
        }
        __syncwarp();
#pragma unroll
        for (int mt = 0; mt < 2; mt++)
#pragma unroll
            for (int ks = 0; ks < 4; ks++) {
                const int r0 = (w * 32 + mt * 16 + g) * QPW + ks * 8 + t;
                qf[mt][ks][0] = qw[r0];
                qf[mt][ks][1] = qw[r0 + 8 * QPW];
                qf[mt][ks][2] = qw[r0 + 4];
                qf[mt][ks][3] = qw[r0 + 8 * QPW + 4];
            }
    }
    __syncthreads();   // protect Q region before K/V staging overwrites it

    float o[2][8][4];
#pragma unroll
    for (int mt = 0; mt < 2; mt++)
#pragma unroll
        for (int nt = 0; nt < 8; nt++)
#pragma unroll
            for (int i = 0; i < 4; i++) o[mt][nt][i] = 0.f;
    float m_[2][2], l_[2][2];
#pragma unroll
    for (int mt = 0; mt < 2; mt++) {
        m_[mt][0] = -INFINITY; m_[mt][1] = -INFINITY;
        l_[mt][0] = 0.f;       l_[mt][1] = 0.f;
    }

    const float* mrow[2][2];
#pragma unroll
    for (int mt = 0; mt < 2; mt++) {
        const float* base = mask + ((long)b * SS + q0 + w * 32 + mt * 16 + g) * SS;
        mrow[mt][0] = base;
        mrow[mt][1] = base + 8L * SS;
    }

    // K staging: kr = tid>>2 (key 0..31), kq = (tid&3)*8 words (16 dh)
    const int kr = tid >> 2, kq = (tid & 3) * 8;
    const __nv_bfloat16* kbase = KB + ((long)((b * HH + h) * SS + kr)) * DHH + kq * 2;
    const uint32_t ksb = smem_u32(KsU);
    const uint32_t ksoff = (kr * KPW + kq) * 4;
    // V staging: vrow = tid>>1 (dh 0..63), half = tid&1 (16 keys)
    const int vrow = tid >> 1, vhalf = tid & 1;
    const __nv_bfloat16* vbase = VT + ((long)((b * HH + h) * DHH + vrow)) * SS + vhalf * 16;
    const uint32_t vtb = smem_u32(VtU);
    const uint32_t vdoff = (vrow * VPW + vhalf * 8) * 4;

    // prologue: stage kb=0 into slot 0
    {
        CP_ASYNC16(ksb + ksoff,      kbase);
        CP_ASYNC16(ksb + ksoff + 16, kbase + 8);
        CP_ASYNC16(vtb + vdoff,      vbase);
        CP_ASYNC16(vtb + vdoff + 16, vbase + 8);
        CP_ASYNC_COMMIT();
        CP_ASYNC_WAIT(0);
    }
    __syncthreads();

    const int NKB = SS / KT;   // 128
    for (int kb = 0; kb < NKB; kb++) {
        const int cur = kb & 1, nxt = cur ^ 1;
        const int k0 = kb * KT;
        const bool more = (kb + 1 < NKB);

        // prefetch next K and Vt tiles (cp.async)
        if (more) {
            const uint32_t kd = ksb + nxt * (KSW * 4) + ksoff;
            CP_ASYNC16(kd,      kbase + (long)(k0 + KT) * DHH);
            CP_ASYNC16(kd + 16, kbase + (long)(k0 + KT) * DHH + 8);
            const uint32_t vd = vtb + nxt * (VTW * 4) + vdoff;
            CP_ASYNC16(vd,      vbase + k0 + KT);
            CP_ASYNC16(vd + 16, vbase + k0 + KT + 8);
            CP_ASYNC_COMMIT();
        }

        const unsigned* Ks = KsU + cur * KSW;
        const unsigned* Vt = VtU + cur * VTW;

        // S = Q @ K^T : bf16 m16n8k16, 4 dh-chunks x 4 key-blocks x 2 mt
        float s[2][4][4];
#pragma unroll
        for (int mt = 0; mt < 2; mt++)
#pragma unroll
            for (int nt = 0; nt < 4; nt++)
#pragma unroll
                for (int i = 0; i < 4; i++) s[mt][nt][i] = 0.f;
#pragma unroll
        for (int ks = 0; ks < 4; ks++) {
#pragma unroll
            for (int nt = 0; nt < 4; nt++) {
                const int cb = (nt * 8 + g) * KPW + ks * 8 + t;
                const unsigned b0 = Ks[cb];
                const unsigned b1 = Ks[cb + 4];
#pragma unroll
                for (int mt = 0; mt < 2; mt++)
                    mma_bf16(s[mt][nt], qf[mt][ks][0], qf[mt][ks][1],
                             qf[mt][ks][2], qf[mt][ks][3], b0, b1);
            }
        }

        // multiplicative mask then streaming softmax (log2 domain); p -> s
#pragma unroll
        for (int mt = 0; mt < 2; mt++) {
            float mx_a = -INFINITY, mx_b = -INFINITY;
#pragma unroll
            for (int nt = 0; nt < 4; nt++) {
                const float2 ma = *(const float2*)(mrow[mt][0] + k0 + nt * 8 + 2 * t);
                const float2 mb = *(const float2*)(mrow[mt][1] + k0 + nt * 8 + 2 * t);
                s[mt][nt][0] *= ma.x; s[mt][nt][1] *= ma.y;
                s[mt][nt][2] *= mb.x; s[mt][nt][3] *= mb.y;
                mx_a = fmaxf(mx_a, fmaxf(s[mt][nt][0], s[mt][nt][1]));
                mx_b = fmaxf(mx_b, fmaxf(s[mt][nt][2], s[mt][nt][3]));
            }
            mx_a = fmaxf(mx_a, __shfl_xor_sync(0xffffffffu, mx_a, 1));
            mx_a = fmaxf(mx_a, __shfl_xor_sync(0xffffffffu, mx_a, 2));
            mx_b = fmaxf(mx_b, __shfl_xor_sync(0xffffffffu, mx_b, 1));
            mx_b = fmaxf(mx_b, __shfl_xor_sync(0xffffffffu, mx_b, 2));
            const float mn_a = fmaxf(m_[mt][0], mx_a), mn_b = fmaxf(m_[mt][1], mx_b);
            const float al_a = ex2(m_[mt][0] - mn_a), al_b = ex2(m_[mt][1] - mn_b);
            float sum_a = 0.f, sum_b = 0.f;
#pragma unroll
            for (int nt = 0; nt < 4; nt++) {
                s[mt][nt][0] = ex2(s[mt][nt][0] - mn_a);
                s[mt][nt][1] = ex2(s[mt][nt][1] - mn_a);
                s[mt][nt][2] = ex2(s[mt][nt][2] - mn_b);
                s[mt][nt][3] = ex2(s[mt][nt][3] - mn_b);
                sum_a += s[mt][nt][0] + s[mt][nt][1];
                sum_b += s[mt][nt][2] + s[mt][nt][3];
            }
            sum_a += __shfl_xor_sync(0xffffffffu, sum_a, 1);
            sum_a += __shfl_xor_sync(0xffffffffu, sum_a, 2);
            sum_b += __shfl_xor_sync(0xffffffffu, sum_b, 1);
            sum_b += __shfl_xor_sync(0xffffffffu, sum_b, 2);
            l_[mt][0] = l_[mt][0] * al_a + sum_a;
            l_[mt][1] = l_[mt][1] * al_b + sum_b;
            m_[mt][0] = mn_a; m_[mt][1] = mn_b;
#pragma unroll
            for (int nt = 0; nt < 8; nt++) {
                o[mt][nt][0] *= al_a; o[mt][nt][1] *= al_a;
                o[mt][nt][2] *= al_b; o[mt][nt][3] *= al_b;
            }
        }

        // O += P @ V in bf16 m16n8k16. P A-frags packed from registers.
#pragma unroll
        for (int kstep = 0; kstep < 2; kstep++) {
            unsigned a[2][4];
#pragma unroll
            for (int mt = 0; mt < 2; mt++) {
                const int n0 = kstep * 2, n1 = n0 + 1;
                a[mt][0] = bfpack(s[mt][n0][0], s[mt][n0][1]);
                a[mt][1] = bfpack(s[mt][n0][2], s[mt][n0][3]);
                a[mt][2] = bfpack(s[mt][n1][0], s[mt][n1][1]);
                a[mt][3] = bfpack(s[mt][n1][2], s[mt][n1][3]);
            }
#pragma unroll
            for (int nt = 0; nt < 8; nt++) {
                const int wi = (nt * 8 + g) * VPW + kstep * 8 + t;
                const unsigned b0 = Vt[wi];
                const unsigned b1 = Vt[wi + 4];
#pragma unroll
                for (int mt = 0; mt < 2; mt++)
                    mma_bf16(o[mt][nt], a[mt][0], a[mt][1], a[mt][2], a[mt][3], b0, b1);
            }
        }

        CP_ASYNC_WAIT(0);
        __syncthreads();
    }

    // finalize + fused residual: x1 = x + O / l
#pragma unroll
    for (int mt = 0; mt < 2; mt++) {
        const float inv_a = 1.f / l_[mt][0], inv_b = 1.f / l_[mt][1];
        const long oa = ((long)(b * SS + q0 + w * 32 + mt * 16 + g)) * DD + hoff;
        const long ob = oa + 8L * DD;
#pragma unroll
        for (int nt = 0; nt < 8; nt++) {
            const int c = nt * 8 + 2 * t;
            const float2 xa = *(const float2*)(x + oa + c);
            const float2 xb = *(const float2*)(x + ob + c);
            *(float2*)(x1 + oa + c) = make_float2(xa.x + o[mt][nt][0] * inv_a,
                                                  xa.y + o[mt][nt][1] * inv_a);
            *(float2*)(x1 + ob + c) = make_float2(xb.x + o[mt][nt][2] * inv_b,
                                                  xb.y + o[mt][nt][3] * inv_b);
        }
    }
}

// ---------------------------------------------------------------------------
// Launch
// ---------------------------------------------------------------------------
extern "C" void kernel_launch(void* const* d_in, const int* in_sizes, int n_in,
                              void* d_out, int out_size)
{
    const float* x    = (const float*)d_in[0];
    const float* mask = (const float*)d_in[1];
    const float* wq   = (const float*)d_in[2];
    const float* bq   = (const float*)d_in[3];
    const float* wk   = (const float*)d_in[4];
    const float* bk   = (const float*)d_in[5];
    const float* wv   = (const float*)d_in[6];
    const float* bv   = (const float*)d_in[7];
    // d_in[8]=wo, d_in[9]=bo unused by the reference forward
    const float* w1   = (const float*)d_in[10];
    const float* b1   = (const float*)d_in[11];
    const float* w2   = (const float*)d_in[12];
    const float* b2   = (const float*)d_in[13];
    const float* g1   = (const float*)d_in[14];
    const float* be1  = (const float*)d_in[15];
    const float* g2   = (const float*)d_in[16];
    const float* be2  = (const float*)d_in[17];
    float* out = (float*)d_out;

    float *l1, *qkv, *x1, *l2, *hb, *wqkv, *bqkv, *w1r, *w2r;
    __nv_bfloat16 *vt, *kb;
    cudaGetSymbolAddress((void**)&l1, g_l1);
    cudaGetSymbolAddress((void**)&qkv, g_qkv);
    cudaGetSymbolAddress((void**)&x1, g_x1);
    cudaGetSymbolAddress((void**)&l2, g_l2);
    cudaGetSymbolAddress((void**)&hb, g_hb);
    cudaGetSymbolAddress((void**)&wqkv, g_wqkv);
    cudaGetSymbolAddress((void**)&bqkv, g_bqkv);
    cudaGetSymbolAddress((void**)&w1r, g_w1r);
    cudaGetSymbolAddress((void**)&w2r, g_w2r);
    cudaGetSymbolAddress((void**)&vt, g_vt);
    cudaGetSymbolAddress((void**)&kb, g_kb);

    cudaFuncSetAttribute(mma_gemm<1>, cudaFuncAttributeMaxDynamicSharedMemorySize, GEMM_SMEM);
    cudaFuncSetAttribute(mma_gemm<2>, cudaFuncAttributeMaxDynamicSharedMemorySize, GEMM_SMEM);
    cudaFuncSetAttribute(mma_gemm<3>, cudaFuncAttributeMaxDynamicSharedMemorySize, GEMM_SMEM);
    cudaFuncSetAttribute(attn_mma_kernel, cudaFuncAttributeMaxDynamicSharedMemorySize, ATTN_SMEM);

    // weight prep: round + concat QKV weights/biases, round w1/w2
    prep_kernel<<<(TOT4 + 255) / 256, 256>>>(wq, wk, wv, wqkv, bq, bk, bv, bqkv,
                                             w1, w1r, w2, w2r);

    // LN1 (rounds output)
    ln_kernel<<<MM, 192>>>(x, g1, be1, l1);

    // Fused QKV projection: [8192,768] @ [768,2304] -> [8192,2304]
    mma_gemm<3><<<dim3(QKVN / 128, MM / 128), 256, GEMM_SMEM>>>(
        l1, wqkv, bqkv, nullptr, qkv, MM, QKVN, DD);

    // K -> bf16 [b][h][key][dh]; V -> transposed bf16 [b][h][dh][key]
    kv_kernel<<<dim3(SS / 32, HH, BB), 256>>>(qkv, vt, kb);

    // Flash attention + residual; head = fastest grid dim for mask L2 reuse
    attn_mma_kernel<<<dim3(HH, SS / QT, BB), 128, ATTN_SMEM>>>(qkv, kb, vt, mask, x, x1);

    // LN2 (rounds output)
    ln_kernel<<<MM, 192>>>(x1, g2, be2, l2);

    // FFN
    mma_gemm<1><<<dim3(DFF / 128, MM / 128), 256, GEMM_SMEM>>>(l2, w1r, b1, nullptr, hb, MM, DFF, DD);
    mma_gemm<2><<<dim3(DD / 128, MM / 128), 256, GEMM_SMEM>>>(hb, w2r, b2, x1, out, MM, DD, DFF);
}

// round 12
// speedup vs baseline: 1.6570x; 1.3221x over previous
#include <cuda_runtime.h>
#include <cuda_fp16.h>
#include <cstdint>
#include <math.h>

// Problem constants
#define BB 2
#define SS 4096
#define DD 768
#define HH 12
#define DHH 64
#define DFF 3072
#define MM (BB*SS)    // 8192
#define QKVN (3*DD)   // 2304

// ---------------------------------------------------------------------------
// Scratch (device globals — allocation-free per harness rules)
// ---------------------------------------------------------------------------
__device__ __half g_l1[MM*DD];          // LN1 out, fp16
__device__ float  g_qkv[MM*QKVN];       // fused Q|K|V (fp32)
__device__ float  g_x1[MM*DD];
__device__ __half g_l2[MM*DD];          // LN2 out, fp16
__device__ __half g_hb[MM*DFF];         // FFN1 out (relu), fp16
__device__ __half g_wqkvp[DD*QKVN];     // packed fp16 [384 kw][2304]
__device__ float  g_bqkv[QKVN];
__device__ __half g_w1p[DD*DFF];        // packed fp16 [384 kw][3072]
__device__ __half g_w2p[DFF*DD];        // packed fp16 [1536 kw][768]
__device__ __half g_vt[(long)BB*HH*DHH*SS];   // V transposed fp16: [b][h][dh][key]
__device__ __half g_kb[(long)BB*HH*SS*DHH];   // K fp16: [b][h][key][dh]

// ---------------------------------------------------------------------------
// Helpers
// ---------------------------------------------------------------------------
__device__ __forceinline__ float ex2(float x) {
    float r;
    asm("ex2.approx.f32 %0, %1;" : "=f"(r) : "f"(x));
    return r;
}

// pack two floats into f16x2: lo -> bits[15:0], hi -> bits[31:16]
__device__ __forceinline__ unsigned hpack(float lo, float hi) {
    unsigned r;
    asm("cvt.rn.f16x2.f32 %0, %1, %2;" : "=r"(r) : "f"(hi), "f"(lo));
    return r;
}

__device__ __forceinline__ uint32_t smem_u32(const void* p) {
    uint32_t a;
    asm("{ .reg .u64 t; cvta.to.shared.u64 t, %1; cvt.u32.u64 %0, t; }"
        : "=r"(a) : "l"(p));
    return a;
}

#define CP_ASYNC16(dst, src) \
    asm volatile("cp.async.cg.shared.global [%0], [%1], 16;" :: "r"((uint32_t)(dst)), "l"(src) : "memory")
#define CP_ASYNC_COMMIT() asm volatile("cp.async.commit_group;" ::: "memory")
#define CP_ASYNC_WAIT(n)  asm volatile("cp.async.wait_group %0;" :: "n"(n) : "memory")

__device__ __forceinline__ void mma_f16(float (&d)[4],
                                        unsigned a0, unsigned a1, unsigned a2, unsigned a3,
                                        unsigned b0, unsigned b1)
{
    asm volatile(
        "mma.sync.aligned.m16n8k16.row.col.f32.f16.f16.f32 "
        "{%0,%1,%2,%3}, {%4,%5,%6,%7}, {%8,%9}, {%0,%1,%2,%3};\n"
        : "+f"(d[0]), "+f"(d[1]), "+f"(d[2]), "+f"(d[3])
        : "r"(a0), "r"(a1), "r"(a2), "r"(a3), "r"(b0), "r"(b1));
}

// ---------------------------------------------------------------------------
// Weight prep: convert+pack to fp16 k-pair words.
//   wqkvp[kw][n] = (w_cat[2kw][n], w_cat[2kw+1][n]),  w_cat = [wq|wk|wv] cols
//   w1p  [kw][n] = (w1[2kw][n],  w1[2kw+1][n])
//   w2p  [kw][n] = (w2[2kw][n],  w2[2kw+1][n])
// Also concat biases (raw fp32).
// ---------------------------------------------------------------------------
#define QROW4 (QKVN / 4)                     // 576
#define WQ4 (DD/2 * QKVN / 4)                // 221184 uint4 outputs
#define W14 (DD/2 * DFF / 4)                 // 294912
#define W24 (DFF/2 * DD / 4)                 // 294912
#define TOTP (WQ4 + W14 + W24)               // 811008

__global__ void prep_kernel(const float* __restrict__ wq, const float* __restrict__ wk,
                            const float* __restrict__ wv, unsigned* __restrict__ wqkvp,
                            const float* __restrict__ bq, const float* __restrict__ bk,
                            const float* __restrict__ bv, float* __restrict__ bqkv,
                            const float* __restrict__ w1, unsigned* __restrict__ w1p,
                            const float* __restrict__ w2, unsigned* __restrict__ w2p)
{
    long i = (long)blockIdx.x * blockDim.x + threadIdx.x;
    if (i >= TOTP) return;

    if (i < QROW4) {   // bias concat (raw fp32; added in fp32 epilogue)
        const int ROW4 = DD / 4;
        const float* bsrc = (i < ROW4) ? (bq + i * 4)
                          : (i < 2 * ROW4) ? (bk + (i - ROW4) * 4)
                          : (bv + (i - 2 * ROW4) * 4);
        ((float4*)bqkv)[i] = *(const float4*)bsrc;
    }

    const float *r0p, *r1p;
    unsigned* outw;
    long wbase;
    if (i < WQ4) {
        const long wi = i * 4;             // word index in [384][2304]
        const int kw = (int)(wi / QKVN);
        const int n  = (int)(wi % QKVN);
        const int sel = n / DD, nn = n - sel * DD;
        const float* w = (sel == 0) ? wq : (sel == 1) ? wk : wv;
        r0p = w + (long)(2 * kw) * DD + nn;
        r1p = r0p + DD;
        outw = wqkvp; wbase = wi;
    } else if (i < WQ4 + W14) {
        const long wi = (i - WQ4) * 4;     // [384][3072]
        const int kw = (int)(wi / DFF);
        const int n  = (int)(wi % DFF);
        r0p = w1 + (long)(2 * kw) * DFF + n;
        r1p = r0p + DFF;
        outw = w1p; wbase = wi;
    } else {
        const long wi = (i - WQ4 - W14) * 4;   // [1536][768]
        const int kw = (int)(wi / DD);
        const int n  = (int)(wi % DD);
        r0p = w2 + (long)(2 * kw) * DD + n;
        r1p = r0p + DD;
        outw = w2p; wbase = wi;
    }
    const float4 r0 = *(const float4*)r0p;
    const float4 r1 = *(const float4*)r1p;
    uint4 o;
    o.x = hpack(r0.x, r1.x);
    o.y = hpack(r0.y, r1.y);
    o.z = hpack(r0.z, r1.z);
    o.w = hpack(r0.w, r1.w);
    *(uint4*)(outw + wbase) = o;
}

// ---------------------------------------------------------------------------
// K/V fp16 prep: V -> g_vt [b][h][dh][key] (transposed), K -> g_kb
// [b][h][key][dh]. Block = 32 keys x 64 dh of one (b,h).
// ---------------------------------------------------------------------------
__global__ void kv_kernel(const float* __restrict__ qkv,
                          __half* __restrict__ vt,
                          __half* __restrict__ kb)
{
    __shared__ float tile[32][68];
    const int k0 = blockIdx.x * 32;
    const int h  = blockIdx.y, b = blockIdx.z;
    const int t  = threadIdx.x;
    {
        const int key = t >> 3, dc = (t & 7) * 8;
        const float* src = qkv + ((long)(b * SS + k0 + key)) * QKVN + 2 * DD + h * DHH + dc;
        *(float4*)&tile[key][dc]     = *(const float4*)src;
        *(float4*)&tile[key][dc + 4] = *(const float4*)(src + 4);
        const float* ksrc = qkv + ((long)(b * SS + k0 + key)) * QKVN + DD + h * DHH + dc;
        float4 ka = *(const float4*)ksrc;
        float4 kc = *(const float4*)(ksrc + 4);
        uint4 kw;
        kw.x = hpack(ka.x, ka.y);  kw.y = hpack(ka.z, ka.w);
        kw.z = hpack(kc.x, kc.y);  kw.w = hpack(kc.z, kc.w);
        *(uint4*)(kb + ((long)((b * HH + h) * SS + k0 + key)) * DHH + dc) = kw;
    }
    __syncthreads();
    {
        const int dh = t >> 2, kc = (t & 3) * 8;
        uint4 ov;
        ov.x = hpack(tile[kc + 0][dh], tile[kc + 1][dh]);
        ov.y = hpack(tile[kc + 2][dh], tile[kc + 3][dh]);
        ov.z = hpack(tile[kc + 4][dh], tile[kc + 5][dh]);
        ov.w = hpack(tile[kc + 6][dh], tile[kc + 7][dh]);
        *(uint4*)(vt + ((long)((b * HH + h) * DHH + dh)) * SS + k0 + kc) = ov;
    }
}

// ---------------------------------------------------------------------------
// LayerNorm: torch-style, unbiased std (ddof=1), normalizer = (sigma + eps).
// 192 threads x float4. Output fp16 (feeds fp16 GEMM A operands).
// ---------------------------------------------------------------------------
__global__ void ln_kernel(const float* __restrict__ x,
                          const float* __restrict__ gamma,
                          const float* __restrict__ beta,
                          __half* __restrict__ out)
{
    const int row = blockIdx.x;
    const int tid = threadIdx.x;
    const float* xr = x + (long)row * DD;

    float4 v = *(const float4*)(xr + tid * 4);
    float s  = v.x + v.y + v.z + v.w;
    float ss = v.x * v.x + v.y * v.y + v.z * v.z + v.w * v.w;
#pragma unroll
    for (int o = 16; o > 0; o >>= 1) {
        s  += __shfl_xor_sync(0xffffffffu, s,  o);
        ss += __shfl_xor_sync(0xffffffffu, ss, o);
    }
    __shared__ float sw[6], ssw[6];
    __shared__ float mu_s, inv_s;
    const int warp = tid >> 5, lane = tid & 31;
    if (lane == 0) { sw[warp] = s; ssw[warp] = ss; }
    __syncthreads();
    if (tid == 0) {
        float ts = 0.f, tss = 0.f;
#pragma unroll
        for (int i = 0; i < 6; i++) { ts += sw[i]; tss += ssw[i]; }
        float mu  = ts / 768.f;
        float var = fmaxf((tss - 768.f * mu * mu) / 767.f, 0.f);
        mu_s  = mu;
        inv_s = 1.f / (sqrtf(var) + 1e-6f);
    }
    __syncthreads();
    const float mu = mu_s, inv = inv_s;
    const float4 gm = *(const float4*)(gamma + tid * 4);
    const float4 bt = *(const float4*)(beta + tid * 4);
    const unsigned w0 = hpack(gm.x * (v.x - mu) * inv + bt.x,
                              gm.y * (v.y - mu) * inv + bt.y);
    const unsigned w1 = hpack(gm.z * (v.z - mu) * inv + bt.z,
                              gm.w * (v.w - mu) * inv + bt.w);
    *(uint2*)(out + (long)row * DD + tid * 4) = make_uint2(w0, w1);
}

// ---------------------------------------------------------------------------
// FP16 tensor-core GEMM, 4-stage cp.async pipeline, one sync per K-iter.
// C = A[M,K](fp16) @ B(packed fp16 [K/2][N] k-pair words) + bias.
// CTA tile 128x128, BK=32 halfs, 256 threads = 8 warps (2x4), warp 64x32,
// mma m16n8k16. EPI: 1 = bias+relu -> fp16 C, 2 = bias+residual -> fp32 C,
// 3 = bias -> fp32 C.
// ---------------------------------------------------------------------------
#define HAP 20                 // A stage pitch (words); row = 16 data words
#define HBP 132                // B stage pitch (words)
#define HASW (128 * HAP)       // 2560 words per A stage
#define HBSW (16 * HBP)        // 2112 words per B stage
#define HNSTG 4
#define HGEMM_SMEM (HNSTG * (HASW + HBSW) * 4)   // 74752 B

template<int EPI>
__global__ __launch_bounds__(256, 2)
void hmma_gemm(const __half* __restrict__ A, const unsigned* __restrict__ Bp,
               const float* __restrict__ bias, const float* __restrict__ res,
               void* __restrict__ Cout, int M, int N, int Kdim)
{
    extern __shared__ unsigned hsm[];
    unsigned* Asm = hsm;
    unsigned* Bsm = hsm + HNSTG * HASW;

    const int tid  = threadIdx.x;
    const int wid  = tid >> 5, lane = tid & 31;
    const int wm   = wid >> 2, wn = wid & 3;
    const int g    = lane >> 2, t = lane & 3;
    const int row0 = blockIdx.y * 128, col0 = blockIdx.x * 128;

    // staging: A row = tid>>1 (0..127), 16 halfs per half-thread pair
    const int ar = tid >> 1, ah = (tid & 1) * 16;       // half offset
    const int br = tid >> 4, bc = (tid & 15) * 8;       // word offset

    const __half* Aptr = A + (long)(row0 + ar) * Kdim + ah;
    const unsigned* Bptr = Bp + (long)br * N + col0 + bc;

    const uint32_t adst = smem_u32(Asm) + (ar * HAP + (tid & 1) * 8) * 4;
    const uint32_t bdst = smem_u32(Bsm) + (br * HBP + bc) * 4;

    float acc[4][4][4];
#pragma unroll
    for (int i = 0; i < 4; i++)
#pragma unroll
        for (int j = 0; j < 4; j++)
#pragma unroll
            for (int k = 0; k < 4; k++) acc[i][j][k] = 0.f;

    const int niter = Kdim / 32;

#pragma unroll
    for (int p = 0; p < 3; p++) {
        const uint32_t ad = adst + p * (HASW * 4);
        const uint32_t bd = bdst + p * (HBSW * 4);
        CP_ASYNC16(ad,      Aptr + (long)p * 32);
        CP_ASYNC16(ad + 16, Aptr + (long)p * 32 + 8);
        CP_ASYNC16(bd,      Bptr + (long)p * 16 * N);
        CP_ASYNC16(bd + 16, Bptr + (long)p * 16 * N + 4);
        CP_ASYNC_COMMIT();
    }

    for (int it = 0; it < niter; it++) {
        if (it + 2 < niter)      { CP_ASYNC_WAIT(2); }
        else if (it + 1 < niter) { CP_ASYNC_WAIT(1); }
        else                     { CP_ASYNC_WAIT(0); }
        __syncthreads();

        if (it + 3 < niter) {
            const int ns = (it + 3) & (HNSTG - 1);
            const uint32_t ad = adst + ns * (HASW * 4);
            const uint32_t bd = bdst + ns * (HBSW * 4);
            CP_ASYNC16(ad,      Aptr + (long)(it + 3) * 32);
            CP_ASYNC16(ad + 16, Aptr + (long)(it + 3) * 32 + 8);
            CP_ASYNC16(bd,      Bptr + (long)(it + 3) * 16 * N);
            CP_ASYNC16(bd + 16, Bptr + (long)(it + 3) * 16 * N + 4);
            CP_ASYNC_COMMIT();
        }

        const int slot = it & (HNSTG - 1);
        const unsigned* as = Asm + slot * HASW;
        const unsigned* bs = Bsm + slot * HBSW;
#pragma unroll
        for (int ks = 0; ks < 2; ks++) {
            unsigned af[4][4];
#pragma unroll
            for (int mt = 0; mt < 4; mt++) {
                const int rb = (wm * 64 + mt * 16 + g) * HAP + ks * 8 + t;
                af[mt][0] = as[rb];
                af[mt][1] = as[rb + 8 * HAP];
                af[mt][2] = as[rb + 4];
                af[mt][3] = as[rb + 8 * HAP + 4];
            }
            unsigned bf[4][2];
#pragma unroll
            for (int nt = 0; nt < 4; nt++) {
                const int cb = (ks * 8 + t) * HBP + wn * 32 + nt * 8 + g;
                bf[nt][0] = bs[cb];
                bf[nt][1] = bs[cb + 4 * HBP];
            }
#pragma unroll
            for (int mt = 0; mt < 4; mt++)
#pragma unroll
                for (int nt = 0; nt < 4; nt++)
                    mma_f16(acc[mt][nt], af[mt][0], af[mt][1], af[mt][2], af[mt][3],
                            bf[nt][0], bf[nt][1]);
        }
    }

    // epilogue
#pragma unroll
    for (int mt = 0; mt < 4; mt++) {
#pragma unroll
        for (int nt = 0; nt < 4; nt++) {
            const int  ccol = col0 + wn * 32 + nt * 8 + 2 * t;
            const long ra   = row0 + wm * 64 + mt * 16 + g;
            const long rb2  = ra + 8;
            const float bx = bias[ccol], by = bias[ccol + 1];
            float v0 = acc[mt][nt][0] + bx;
            float v1 = acc[mt][nt][1] + by;
            float v2 = acc[mt][nt][2] + bx;
            float v3 = acc[mt][nt][3] + by;
            if (EPI == 1) {
                // relu -> fp16 output
                unsigned* Ch = (unsigned*)Cout;
                Ch[(ra  * N + ccol) >> 1] = hpack(fmaxf(v0, 0.f), fmaxf(v1, 0.f));
                Ch[(rb2 * N + ccol) >> 1] = hpack(fmaxf(v2, 0.f), fmaxf(v3, 0.f));
            } else {
                float* Cf = (float*)Cout;
                if (EPI == 2) {
                    const float2 r0 = *(const float2*)(res + ra  * N + ccol);
                    const float2 r1 = *(const float2*)(res + rb2 * N + ccol);
                    v0 += r0.x; v1 += r0.y; v2 += r1.x; v3 += r1.y;
                }
                *(float2*)(Cf + ra  * N + ccol) = make_float2(v0, v1);
                *(float2*)(Cf + rb2 * N + ccol) = make_float2(v2, v3);
            }
        }
    }
}

// ---------------------------------------------------------------------------
// Flash attention, all-fp16 tensor path. QK^T and PV both m16n8k16 f16;
// fp32 softmax state. Q-tile 128 rows, 128 threads = 4 warps, warp w owns
// 32 q-rows. Q packed f16x2 in registers; P packed in registers (no smem);
// K (fp16 [key][dh]) and Vt (fp16 [dh][key]) double-buffered via cp.async.
// smem 19.5 KB. Fuses residual: x1 = x + ctx.
// ---------------------------------------------------------------------------
#define QPW 36
#define KPW 36
#define VPW 20
#define QT 128
#define KT 32
#define KSW (KT * KPW)                 // 1152 words per K stage
#define VTW (DHH * VPW)                // 1280 words per V stage
#define ATTN_SMEM ((2 * KSW + 2 * VTW) * 4)   // 19456 B

__global__ __launch_bounds__(128, 2)
void attn_mma_kernel(const float* __restrict__ QKV,
                     const __half* __restrict__ KB,
                     const __half* __restrict__ VT,
                     const float* __restrict__ mask,
                     const float* __restrict__ x, float* __restrict__ x1)
{
    extern __shared__ float sm[];
    unsigned* KsU = (unsigned*)sm;            // 2 x [32][KPW]
    unsigned* VtU = (unsigned*)sm + 2 * KSW;  // 2 x [64][VPW]

    const int tid = threadIdx.x;
    const int w = tid >> 5, lane = tid & 31;
    const int g = lane >> 2, t = lane & 3;
    const int h = blockIdx.x, qb = blockIdx.y, b = blockIdx.z;
    const int q0 = qb * QT, hoff = h * DHH;

    const float qscale = 0.125f * 1.4426950408889634f;  // 1/sqrt(64)*log2(e)

    // stage Q packed f16x2 (scale folded) through smem, pull A-frags to regs.
    unsigned qf[2][4][4];
    {
        unsigned* qw = (unsigned*)sm;
        const float* qsrc = QKV + ((long)(b * SS + q0 + tid)) * QKVN + hoff;
#pragma unroll
        for (int i = 0; i < 8; i++) {
            float4 a = *(const float4*)(qsrc + i * 8);
            float4 c = *(const float4*)(qsrc + i * 8 + 4);
            uint4 pw;
            pw.x = hpack(a.x * qscale, a.y * qscale);
            pw.y = hpack(a.z * qscale, a.w * qscale);
            pw.z = hpack(c.x * qscale, c.y * qscale);
            pw.w = hpack(c.z * qscale, c.w * qscale);
            *(uint4*)&qw[tid * QPW + i * 4] = pw;
        }
        __syncwarp();
#pragma unroll
        for (int mt = 0; mt < 2; mt++)
#pragma unroll
            for (int ks = 0; ks < 4; ks++) {
                const int r0 = (w * 32 + mt * 16 + g) * QPW + ks * 8 + t;
                qf[mt][ks][0] = qw[r0];
                qf[mt][ks][1] = qw[r0 + 8 * QPW];
                qf[mt][ks][2] = qw[r0 + 4];
                qf[mt][ks][3] = qw[r0 + 8 * QPW + 4];
            }
    }
    __syncthreads();

    float o[2][8][4];
#pragma unroll
    for (int mt = 0; mt < 2; mt++)
#pragma unroll
        for (int nt = 0; nt < 8; nt++)
#pragma unroll
            for (int i = 0; i < 4; i++) o[mt][nt][i] = 0.f;
    float m_[2][2], l_[2][2];
#pragma unroll
    for (int mt = 0; mt < 2; mt++) {
        m_[mt][0] = -INFINITY; m_[mt][1] = -INFINITY;
        l_[mt][0] = 0.f;       l_[mt][1] = 0.f;
    }

    const float* mrow[2][2];
#pragma unroll
    for (int mt = 0; mt < 2; mt++) {
        const float* base = mask + ((long)b * SS + q0 + w * 32 + mt * 16 + g) * SS;
        mrow[mt][0] = base;
        mrow[mt][1] = base + 8L * SS;
    }

    // K staging: kr = tid>>2 (key 0..31), kq = (tid&3)*8 words (16 dh)
    const int kr = tid >> 2, kq = (tid & 3) * 8;
    const __half* kbase = KB + ((long)((b * HH + h) * SS + kr)) * DHH + kq * 2;
    const uint32_t ksb = smem_u32(KsU);
    const uint32_t ksoff = (kr * KPW + kq) * 4;
    // V staging: vrow = tid>>1 (dh 0..63), half = tid&1 (16 keys)
    const int vrow = tid >> 1, vhalf = tid & 1;
    const __half* vbase = VT + ((long)((b * HH + h) * DHH + vrow)) * SS + vhalf * 16;
    const uint32_t vtb = smem_u32(VtU);
    const uint32_t vdoff = (vrow * VPW + vhalf * 8) * 4;

    // prologue: stage kb=0 into slot 0
    {
        CP_ASYNC16(ksb + ksoff,      kbase);
        CP_ASYNC16(ksb + ksoff + 16, kbase + 8);
        CP_ASYNC16(vtb + vdoff,      vbase);
        CP_ASYNC16(vtb + vdoff + 16, vbase + 8);
        CP_ASYNC_COMMIT();
        CP_ASYNC_WAIT(0);
    }
    __syncthreads();

    const int NKB = SS / KT;   // 128
    for (int kb = 0; kb < NKB; kb++) {
        const int cur = kb & 1, nxt = cur ^ 1;
        const int k0 = kb * KT;
        const bool more = (kb + 1 < NKB);

        if (more) {
            const uint32_t kd = ksb + nxt * (KSW * 4) + ksoff;
            CP_ASYNC16(kd,      kbase + (long)(k0 + KT) * DHH);
            CP_ASYNC16(kd + 16, kbase + (long)(k0 + KT) * DHH + 8);
            const uint32_t vd = vtb + nxt * (VTW * 4) + vdoff;
            CP_ASYNC16(vd,      vbase + k0 + KT);
            CP_ASYNC16(vd + 16, vbase + k0 + KT + 8);
            CP_ASYNC_COMMIT();
        }

        const unsigned* Ks = KsU + cur * KSW;
        const unsigned* Vt = VtU + cur * VTW;

        // S = Q @ K^T : f16 m16n8k16
        float s[2][4][4];
#pragma unroll
        for (int mt = 0; mt < 2; mt++)
#pragma unroll
            for (int nt = 0; nt < 4; nt++)
#pragma unroll
                for (int i = 0; i < 4; i++) s[mt][nt][i] = 0.f;
#pragma unroll
        for (int ks = 0; ks < 4; ks++) {
#pragma unroll
            for (int nt = 0; nt < 4; nt++) {
                const int cb = (nt * 8 + g) * KPW + ks * 8 + t;
                const unsigned b0 = Ks[cb];
                const unsigned b1 = Ks[cb + 4];
#pragma unroll
                for (int mt = 0; mt < 2; mt++)
                    mma_f16(s[mt][nt], qf[mt][ks][0], qf[mt][ks][1],
                            qf[mt][ks][2], qf[mt][ks][3], b0, b1);
            }
        }

        // multiplicative mask then streaming softmax (log2 domain); p -> s
#pragma unroll
        for (int mt = 0; mt < 2; mt++) {
            float mx_a = -INFINITY, mx_b = -INFINITY;
#pragma unroll
            for (int nt = 0; nt < 4; nt++) {
                const float2 ma = *(const float2*)(mrow[mt][0] + k0 + nt * 8 + 2 * t);
                const float2 mb = *(const float2*)(mrow[mt][1] + k0 + nt * 8 + 2 * t);
                s[mt][nt][0] *= ma.x; s[mt][nt][1] *= ma.y;
                s[mt][nt][2] *= mb.x; s[mt][nt][3] *= mb.y;
                mx_a = fmaxf(mx_a, fmaxf(s[mt][nt][0], s[mt][nt][1]));
                mx_b = fmaxf(mx_b, fmaxf(s[mt][nt][2], s[mt][nt][3]));
            }
            mx_a = fmaxf(mx_a, __shfl_xor_sync(0xffffffffu, mx_a, 1));
            mx_a = fmaxf(mx_a, __shfl_xor_sync(0xffffffffu, mx_a, 2));
            mx_b = fmaxf(mx_b, __shfl_xor_sync(0xffffffffu, mx_b, 1));
            mx_b = fmaxf(mx_b, __shfl_xor_sync(0xffffffffu, mx_b, 2));
            const float mn_a = fmaxf(m_[mt][0], mx_a), mn_b = fmaxf(m_[mt][1], mx_b);
            const float al_a = ex2(m_[mt][0] - mn_a), al_b = ex2(m_[mt][1] - mn_b);
            float sum_a = 0.f, sum_b = 0.f;
#pragma unroll
            for (int nt = 0; nt < 4; nt++) {
                s[mt][nt][0] = ex2(s[mt][nt][0] - mn_a);
                s[mt][nt][1] = ex2(s[mt][nt][1] - mn_a);
                s[mt][nt][2] = ex2(s[mt][nt][2] - mn_b);
                s[mt][nt][3] = ex2(s[mt][nt][3] - mn_b);
                sum_a += s[mt][nt][0] + s[mt][nt][1];
                sum_b += s[mt][nt][2] + s[mt][nt][3];
            }
            sum_a += __shfl_xor_sync(0xffffffffu, sum_a, 1);
            sum_a += __shfl_xor_sync(0xffffffffu, sum_a, 2);
            sum_b += __shfl_xor_sync(0xffffffffu, sum_b, 1);
            sum_b += __shfl_xor_sync(0xffffffffu, sum_b, 2);
            l_[mt][0] = l_[mt][0] * al_a + sum_a;
            l_[mt][1] = l_[mt][1] * al_b + sum_b;
            m_[mt][0] = mn_a; m_[mt][1] = mn_b;
#pragma unroll
            for (int nt = 0; nt < 8; nt++) {
                o[mt][nt][0] *= al_a; o[mt][nt][1] *= al_a;
                o[mt][nt][2] *= al_b; o[mt][nt][3] *= al_b;
            }
        }

        // O += P @ V in f16 m16n8k16, P packed from registers.
#pragma unroll
        for (int kstep = 0; kstep < 2; kstep++) {
            unsigned a[2][4];
#pragma unroll
            for (int mt = 0; mt < 2; mt++) {
                const int n0 = kstep * 2, n1 = n0 + 1;
                a[mt][0] = hpack(s[mt][n0][0], s[mt][n0][1]);
                a[mt][1] = hpack(s[mt][n0][2], s[mt][n0][3]);
                a[mt][2] = hpack(s[mt][n1][0], s[mt][n1][1]);
                a[mt][3] = hpack(s[mt][n1][2], s[mt][n1][3]);
            }
#pragma unroll
            for (int nt = 0; nt < 8; nt++) {
                const int wi = (nt * 8 + g) * VPW + kstep * 8 + t;
                const unsigned b0 = Vt[wi];
                const unsigned b1 = Vt[wi + 4];
#pragma unroll
                for (int mt = 0; mt < 2; mt++)
                    mma_f16(o[mt][nt], a[mt][0], a[mt][1], a[mt][2], a[mt][3], b0, b1);
            }
        }

        CP_ASYNC_WAIT(0);
        __syncthreads();
    }

    // finalize + fused residual: x1 = x + O / l
#pragma unroll
    for (int mt = 0; mt < 2; mt++) {
        const float inv_a = 1.f / l_[mt][0], inv_b = 1.f / l_[mt][1];
        const long oa = ((long)(b * SS + q0 + w * 32 + mt * 16 + g)) * DD + hoff;
        const long ob = oa + 8L * DD;
#pragma unroll
        for (int nt = 0; nt < 8; nt++) {
            const int c = nt * 8 + 2 * t;
            const float2 xa = *(const float2*)(x + oa + c);
            const float2 xb = *(const float2*)(x + ob + c);
            *(float2*)(x1 + oa + c) = make_float2(xa.x + o[mt][nt][0] * inv_a,
                                                  xa.y + o[mt][nt][1] * inv_a);
            *(float2*)(x1 + ob + c) = make_float2(xb.x + o[mt][nt][2] * inv_b,
                                                  xb.y + o[mt][nt][3] * inv_b);
        }
    }
}

// ---------------------------------------------------------------------------
// Launch
// ---------------------------------------------------------------------------
extern "C" void kernel_launch(void* const* d_in, const int* in_sizes, int n_in,
                              void* d_out, int out_size)
{
    const float* x    = (const float*)d_in[0];
    const float* mask = (const float*)d_in[1];
    const float* wq   = (const float*)d_in[2];
    const float* bq   = (const float*)d_in[3];
    const float* wk   = (const float*)d_in[4];
    const float* bk   = (const float*)d_in[5];
    const float* wv   = (const float*)d_in[6];
    const float* bv   = (const float*)d_in[7];
    // d_in[8]=wo, d_in[9]=bo unused by the reference forward
    const float* w1   = (const float*)d_in[10];
    const float* b1   = (const float*)d_in[11];
    const float* w2   = (const float*)d_in[12];
    const float* b2   = (const float*)d_in[13];
    const float* g1   = (const float*)d_in[14];
    const float* be1  = (const float*)d_in[15];
    const float* g2   = (const float*)d_in[16];
    const float* be2  = (const float*)d_in[17];
    float* out = (float*)d_out;

    float *qkv, *x1, *bqkv;
    __half *l1, *l2, *hb, *wqkvp, *w1p, *w2p, *vt, *kb;
    cudaGetSymbolAddress((void**)&l1, g_l1);
    cudaGetSymbolAddress((void**)&qkv, g_qkv);
    cudaGetSymbolAddress((void**)&x1, g_x1);
    cudaGetSymbolAddress((void**)&l2, g_l2);
    cudaGetSymbolAddress((void**)&hb, g_hb);
    cudaGetSymbolAddress((void**)&wqkvp, g_wqkvp);
    cudaGetSymbolAddress((void**)&bqkv, g_bqkv);
    cudaGetSymbolAddress((void**)&w1p, g_w1p);
    cudaGetSymbolAddress((void**)&w2p, g_w2p);
    cudaGetSymbolAddress((void**)&vt, g_vt);
    cudaGetSymbolAddress((void**)&kb, g_kb);

    cudaFuncSetAttribute(hmma_gemm<1>, cudaFuncAttributeMaxDynamicSharedMemorySize, HGEMM_SMEM);
    cudaFuncSetAttribute(hmma_gemm<2>, cudaFuncAttributeMaxDynamicSharedMemorySize, HGEMM_SMEM);
    cudaFuncSetAttribute(hmma_gemm<3>, cudaFuncAttributeMaxDynamicSharedMemorySize, HGEMM_SMEM);
    cudaFuncSetAttribute(attn_mma_kernel, cudaFuncAttributeMaxDynamicSharedMemorySize, ATTN_SMEM);

    // weight prep: fp16 pack + QKV concat; bias concat
    prep_kernel<<<(TOTP + 255) / 256, 256>>>(wq, wk, wv, (unsigned*)wqkvp,
                                             bq, bk, bv, bqkv,
                                             w1, (unsigned*)w1p,
                                             w2, (unsigned*)w2p);

    // LN1 (fp16 out)
    ln_kernel<<<MM, 192>>>(x, g1, be1, l1);

    // Fused QKV projection (fp16): [8192,768] @ [768,2304] -> fp32 [8192,2304]
    hmma_gemm<3><<<dim3(QKVN / 128, MM / 128), 256, HGEMM_SMEM>>>(
        l1, (const unsigned*)wqkvp, bqkv, nullptr, qkv, MM, QKVN, DD);

    // K -> fp16 [b][h][key][dh]; V -> transposed fp16 [b][h][dh][key]
    kv_kernel<<<dim3(SS / 32, HH, BB), 256>>>(qkv, vt, kb);

    // Flash attention + residual; head = fastest grid dim for mask L2 reuse
    attn_mma_kernel<<<dim3(HH, SS / QT, BB), 128, ATTN_SMEM>>>(qkv, kb, vt, mask, x, x1);

    // LN2 (fp16 out)
    ln_kernel<<<MM, 192>>>(x1, g2, be2, l2);

    // FFN (fp16): FFN1 relu -> fp16 hb; FFN2 + residual -> fp32 out
    hmma_gemm<1><<<dim3(DFF / 128, MM / 128), 256, HGEMM_SMEM>>>(
        l2, (const unsigned*)w1p, b1, nullptr, hb, MM, DFF, DD);
    hmma_gemm<2><<<dim3(DD / 128, MM / 128), 256, HGEMM_SMEM>>>(
        hb, (const unsigned*)w2p, b2, x1, out, MM, DD, DFF);
}